// round 12
// baseline (speedup 1.0000x reference)
#include <cuda_runtime.h>
#include <cuda_bf16.h>
#include <cstdint>
#include <math.h>

// ---------------------------------------------------------------------------
// Problem constants
// ---------------------------------------------------------------------------
#define BATCH 8192
#define TDIM  512
#define FDIM  2048
#define NATTN 4
#define NMLP  2

// weight scratch layout (element offsets into g_wh / g_wl)
// [MS_OFF)  : packed mu/sig, per attn block 1024x512, rows interleaved
//             (even row r -> mu_w[r/2], odd row r -> sg_w[r/2])
#define MS_OFF  0
#define AW1_OFF 2097152
#define AW2_OFF 6291456
#define MW1_OFF 10485760
#define MW2_OFF 12582912
#define WTOTAL  14680064

// ---------------------------------------------------------------------------
// Device scratch (static — no allocation at launch time)
// ---------------------------------------------------------------------------
__device__ __nv_bfloat16 g_wh[WTOTAL];          // 29 MB  weight hi
__device__ __nv_bfloat16 g_wl[WTOTAL];          // 29 MB  weight lo
__device__ float         g_Q [BATCH * TDIM];    // 16 MB  residual stream
__device__ float         g_H [BATCH * TDIM * 8];// 128 MB RFF tokens (precomputed)
__device__ __nv_bfloat16 g_hh[BATCH * TDIM];    // LN output hi
__device__ __nv_bfloat16 g_hl[BATCH * TDIM];    // LN output lo
__device__ __nv_bfloat16 g_th[BATCH * FDIM];    // FFN mid hi
__device__ __nv_bfloat16 g_tl[BATCH * FDIM];    // FFN mid lo

// ---------------------------------------------------------------------------
// Helpers
// ---------------------------------------------------------------------------
__device__ __forceinline__ float silu_f(float x) {
    return x / (1.0f + __expf(-x));
}

__device__ __forceinline__ void split_bf16(float x, __nv_bfloat16& hi, __nv_bfloat16& lo) {
    hi = __float2bfloat16_rn(x);
    lo = __float2bfloat16_rn(x - __bfloat162float(hi));
}

__device__ __forceinline__ void mma_bf16(float* d, const uint32_t* a, const uint32_t* b) {
    asm volatile(
        "mma.sync.aligned.m16n8k16.row.col.f32.bf16.bf16.f32 "
        "{%0,%1,%2,%3}, {%4,%5,%6,%7}, {%8,%9}, {%0,%1,%2,%3};\n"
        : "+f"(d[0]), "+f"(d[1]), "+f"(d[2]), "+f"(d[3])
        : "r"(a[0]), "r"(a[1]), "r"(a[2]), "r"(a[3]), "r"(b[0]), "r"(b[1]));
}

__device__ __forceinline__ void cp16(uint32_t dst, const void* src) {
    asm volatile("cp.async.cg.shared.global [%0], [%1], 16;\n" :: "r"(dst), "l"(src));
}
__device__ __forceinline__ void cp_commit() {
    asm volatile("cp.async.commit_group;\n");
}
template<int N> __device__ __forceinline__ void cp_wait() {
    asm volatile("cp.async.wait_group %0;\n" :: "n"(N));
}

__device__ __forceinline__ void ldsm4(uint32_t& r0, uint32_t& r1, uint32_t& r2,
                                      uint32_t& r3, uint32_t addr) {
    asm volatile("ldmatrix.sync.aligned.m8n8.x4.shared.b16 {%0,%1,%2,%3}, [%4];\n"
                 : "=r"(r0), "=r"(r1), "=r"(r2), "=r"(r3) : "r"(addr));
}

// XOR-swizzled smem layout: per array, row r holds 32 bf16 = 64B = 4 chunks
// of 16B; logical chunk c lives at physical chunk c ^ ((r>>1)&3).
// ldmatrix phase (8 lanes = 8 consecutive rows, fixed c) and staging writes
// (warp = 8 rows x 4 chunks) both cover all 32 banks exactly: conflict-free.
__device__ __forceinline__ uint32_t swz(int r, int c) {
    return (uint32_t)(r * 64 + ((c ^ ((r >> 1) & 3)) * 16));
}

// ---------------------------------------------------------------------------
// GEMM mainloop WIDE (bf16x3 split): CTA tile 128(M) x 256(N), 256 threads,
// 1 CTA/SM. Warp grid 2m x 4n, warp tile 64x64.
//   bytes/MAC: (128KB ldsm reads + 48KB stage writes) / 3.15M MACs = 0.056
//   vs 0.082 for the 128x128 config -> smem-crossbar-bound GEMM gets ~1.4x.
// 3-stage cp.async ring (144KB), ONE __syncthreads per K-tile, prefetch
// distance 2. acc += Ah*Wh + Ah*Wl + Al*Wh; term-major (reuse distance 8).
// ---------------------------------------------------------------------------
#define A_ARR   (128 * 64)             // 8192 B per A array
#define B_ARR   (256 * 64)             // 16384 B per B array
#define OFF_AH  0
#define OFF_AL  (A_ARR)
#define OFF_WH  (2 * A_ARR)
#define OFF_WL  (2 * A_ARR + B_ARR)
#define STAGE_BYTES (2 * A_ARR + 2 * B_ARR)   // 49152
#define NSTAGE 3
#define SMEM_BYTES  (NSTAGE * STAGE_BYTES)    // 147456
#define NTHREADS 256
#define BN 256

template<int K>
__device__ __forceinline__ void gemm_mainloop(
    const __nv_bfloat16* __restrict__ Ah, const __nv_bfloat16* __restrict__ Al,
    const __nv_bfloat16* __restrict__ Wh, const __nv_bfloat16* __restrict__ Wl,
    int rowBase, int colBase, uint32_t sb, float acc[4][8][4])
{
    const int tid  = threadIdx.x;
    const int lane = tid & 31;
    const int warp = tid >> 5;
    const int warpM = warp & 1;
    const int warpN = warp >> 1;

    // staging: thread covers chunk col q of A rows {r0, r0+64} and
    // B rows {r0, r0+64, r0+128, r0+192}
    const int r0 = tid >> 2, q = tid & 3;
    const uint32_t offA0 = swz(r0, q),       offA1 = swz(r0 + 64, q);
    const uint32_t offB0 = swz(r0, q),       offB1 = swz(r0 + 64, q);
    const uint32_t offB2 = swz(r0 + 128, q), offB3 = swz(r0 + 192, q);
    const __nv_bfloat16* pah0 = Ah + (size_t)(rowBase + r0) * K + q * 8;
    const __nv_bfloat16* pah1 = Ah + (size_t)(rowBase + r0 + 64) * K + q * 8;
    const __nv_bfloat16* pal0 = Al + (size_t)(rowBase + r0) * K + q * 8;
    const __nv_bfloat16* pal1 = Al + (size_t)(rowBase + r0 + 64) * K + q * 8;
    const __nv_bfloat16* pwh0 = Wh + (size_t)(colBase + r0) * K + q * 8;
    const __nv_bfloat16* pwh1 = Wh + (size_t)(colBase + r0 + 64) * K + q * 8;
    const __nv_bfloat16* pwh2 = Wh + (size_t)(colBase + r0 + 128) * K + q * 8;
    const __nv_bfloat16* pwh3 = Wh + (size_t)(colBase + r0 + 192) * K + q * 8;
    const __nv_bfloat16* pwl0 = Wl + (size_t)(colBase + r0) * K + q * 8;
    const __nv_bfloat16* pwl1 = Wl + (size_t)(colBase + r0 + 64) * K + q * 8;
    const __nv_bfloat16* pwl2 = Wl + (size_t)(colBase + r0 + 128) * K + q * 8;
    const __nv_bfloat16* pwl3 = Wl + (size_t)(colBase + r0 + 192) * K + q * 8;

    auto stage = [&](int s, int k0) {
        const uint32_t base = sb + s * STAGE_BYTES;
        cp16(base + OFF_AH + offA0, pah0 + k0);
        cp16(base + OFF_AH + offA1, pah1 + k0);
        cp16(base + OFF_AL + offA0, pal0 + k0);
        cp16(base + OFF_AL + offA1, pal1 + k0);
        cp16(base + OFF_WH + offB0, pwh0 + k0);
        cp16(base + OFF_WH + offB1, pwh1 + k0);
        cp16(base + OFF_WH + offB2, pwh2 + k0);
        cp16(base + OFF_WH + offB3, pwh3 + k0);
        cp16(base + OFF_WL + offB0, pwl0 + k0);
        cp16(base + OFF_WL + offB1, pwl1 + k0);
        cp16(base + OFF_WL + offB2, pwl2 + k0);
        cp16(base + OFF_WL + offB3, pwl3 + k0);
        cp_commit();
    };

    // fragment load offsets
    const int ldrow = lane & 15;
    const int khalf = lane >> 4;                 // 16B column within k-chunk
    uint32_t offA[2][4], offB[2][4];
#pragma unroll
    for (int kc = 0; kc < 2; kc++) {
        const int c = kc * 2 + khalf;
#pragma unroll
        for (int mi = 0; mi < 4; mi++)
            offA[kc][mi] = swz(warpM * 64 + mi * 16 + ldrow, c);
#pragma unroll
        for (int p = 0; p < 4; p++)
            offB[kc][p]  = swz(warpN * 64 + p * 16 + ldrow, c);
    }

    const int nt = K / 32;
    stage(0, 0);
    stage(1, 32);

    for (int it = 0; it < nt; it++) {
        if (it < nt - 1) cp_wait<1>(); else cp_wait<0>();
        __syncthreads();
        if (it + 2 < nt) stage((it + 2) % NSTAGE, (it + 2) * 32);

        const uint32_t base = sb + (it % NSTAGE) * STAGE_BYTES;
#pragma unroll
        for (int kc = 0; kc < 2; kc++) {
            uint32_t bhi[8][2], blo[8][2];
#pragma unroll
            for (int p = 0; p < 4; p++) {
                uint32_t r0v, r1v, r2v, r3v;
                ldsm4(r0v, r1v, r2v, r3v, base + OFF_WH + offB[kc][p]);
                bhi[2 * p][0] = r0v; bhi[2 * p + 1][0] = r1v;
                bhi[2 * p][1] = r2v; bhi[2 * p + 1][1] = r3v;
                ldsm4(r0v, r1v, r2v, r3v, base + OFF_WL + offB[kc][p]);
                blo[2 * p][0] = r0v; blo[2 * p + 1][0] = r1v;
                blo[2 * p][1] = r2v; blo[2 * p + 1][1] = r3v;
            }
#pragma unroll
            for (int mi = 0; mi < 4; mi++) {
                uint32_t ah[4], al[4];
                ldsm4(ah[0], ah[1], ah[2], ah[3], base + OFF_AH + offA[kc][mi]);
                ldsm4(al[0], al[1], al[2], al[3], base + OFF_AL + offA[kc][mi]);
                // term-major: 8 independent MMAs between acc reuses
#pragma unroll
                for (int ni = 0; ni < 8; ni++) mma_bf16(acc[mi][ni], ah, bhi[ni]);
#pragma unroll
                for (int ni = 0; ni < 8; ni++) mma_bf16(acc[mi][ni], ah, blo[ni]);
#pragma unroll
                for (int ni = 0; ni < 8; ni++) mma_bf16(acc[mi][ni], al, bhi[ni]);
            }
        }
    }
}

// ---------------------------------------------------------------------------
// FFN first GEMM: t = silu(h @ W1^T + b1), bf16 hi/lo split output
// ---------------------------------------------------------------------------
template<int K, int N>
__global__ __launch_bounds__(NTHREADS, 1) void gemm_ffn1(
    const __nv_bfloat16* __restrict__ Ah, const __nv_bfloat16* __restrict__ Al,
    const __nv_bfloat16* __restrict__ Wh, const __nv_bfloat16* __restrict__ Wl,
    const float* __restrict__ bias,
    __nv_bfloat16* __restrict__ Ch, __nv_bfloat16* __restrict__ Cl)
{
    extern __shared__ __align__(128) uint32_t smem[];
    const uint32_t sb = (uint32_t)__cvta_generic_to_shared(smem);
    const int rowBase = blockIdx.y * 128;
    const int colBase = blockIdx.x * BN;

    float acc[4][8][4];
#pragma unroll
    for (int mi = 0; mi < 4; mi++)
#pragma unroll
        for (int ni = 0; ni < 8; ni++)
#pragma unroll
            for (int r = 0; r < 4; r++) acc[mi][ni][r] = 0.0f;

    gemm_mainloop<K>(Ah, Al, Wh, Wl, rowBase, colBase, sb, acc);

    const int lane = threadIdx.x & 31;
    const int warp = threadIdx.x >> 5;
    const int warpM = warp & 1, warpN = warp >> 1;
    const int g = lane >> 2, tg = lane & 3;
#pragma unroll
    for (int mi = 0; mi < 4; mi++) {
#pragma unroll
        for (int ni = 0; ni < 8; ni++) {
            int m0 = rowBase + warpM * 64 + mi * 16 + g;
            int n0 = colBase + warpN * 64 + ni * 8 + tg * 2;
            float bn0 = bias[n0], bn1 = bias[n0 + 1];
#pragma unroll
            for (int h = 0; h < 2; h++) {
                int m = m0 + h * 8;
                float u0 = silu_f(acc[mi][ni][2 * h + 0] + bn0);
                float u1 = silu_f(acc[mi][ni][2 * h + 1] + bn1);
                size_t idx = (size_t)m * N + n0;
                __nv_bfloat16 h0, l0, h1, l1;
                split_bf16(u0, h0, l0);
                split_bf16(u1, h1, l1);
                *(__nv_bfloat162*)(Ch + idx) = __halves2bfloat162(h0, h1);
                *(__nv_bfloat162*)(Cl + idx) = __halves2bfloat162(l0, l1);
            }
        }
    }
}

// ---------------------------------------------------------------------------
// FFN second GEMM: Q += t @ W2^T + b2  (residual, in place)
// ---------------------------------------------------------------------------
template<int K, int N>
__global__ __launch_bounds__(NTHREADS, 1) void gemm_ffn2(
    const __nv_bfloat16* __restrict__ Ah, const __nv_bfloat16* __restrict__ Al,
    const __nv_bfloat16* __restrict__ Wh, const __nv_bfloat16* __restrict__ Wl,
    const float* __restrict__ bias, float* __restrict__ C)
{
    extern __shared__ __align__(128) uint32_t smem[];
    const uint32_t sb = (uint32_t)__cvta_generic_to_shared(smem);
    const int rowBase = blockIdx.y * 128;
    const int colBase = blockIdx.x * BN;

    float acc[4][8][4];
#pragma unroll
    for (int mi = 0; mi < 4; mi++)
#pragma unroll
        for (int ni = 0; ni < 8; ni++)
#pragma unroll
            for (int r = 0; r < 4; r++) acc[mi][ni][r] = 0.0f;

    gemm_mainloop<K>(Ah, Al, Wh, Wl, rowBase, colBase, sb, acc);

    const int lane = threadIdx.x & 31;
    const int warp = threadIdx.x >> 5;
    const int warpM = warp & 1, warpN = warp >> 1;
    const int g = lane >> 2, tg = lane & 3;
#pragma unroll
    for (int mi = 0; mi < 4; mi++) {
#pragma unroll
        for (int ni = 0; ni < 8; ni++) {
            int m0 = rowBase + warpM * 64 + mi * 16 + g;
            int n0 = colBase + warpN * 64 + ni * 8 + tg * 2;
            float bn0 = bias[n0], bn1 = bias[n0 + 1];
#pragma unroll
            for (int h = 0; h < 2; h++) {
                int m = m0 + h * 8;
                size_t idx = (size_t)m * N + n0;
                C[idx]     = acc[mi][ni][2 * h + 0] + bn0 + C[idx];
                C[idx + 1] = acc[mi][ni][2 * h + 1] + bn1 + C[idx + 1];
            }
        }
    }
}

// ---------------------------------------------------------------------------
// Fused mu/sig GEMM + attention gather (H precomputed in g_H).
// W is the packed interleaved [1024, 512] matrix (even rows mu, odd rows sig)
// so each epilogue pair (n0, n0+1) = (mu, sig) for token n = n0/2. Epilogue:
//   mu = tanh(v0 + mu_b[n]); sg = v1 + sg_b[n]
//   Q[m,n] += sum_k exp(-0.5 (G[n,k]-mu)^2 / (sg^2+eps)) * H[m,n,k]
// ---------------------------------------------------------------------------
__global__ __launch_bounds__(NTHREADS, 1) void gemm_musig(
    const __nv_bfloat16* __restrict__ Ah, const __nv_bfloat16* __restrict__ Al,
    const __nv_bfloat16* __restrict__ Wh, const __nv_bfloat16* __restrict__ Wl,
    const float* __restrict__ mu_b, const float* __restrict__ sg_b,
    const float* __restrict__ G, float* __restrict__ Q)
{
    extern __shared__ __align__(128) uint32_t smem[];
    const uint32_t sb = (uint32_t)__cvta_generic_to_shared(smem);
    const int rowBase = blockIdx.y * 128;
    const int colBase = blockIdx.x * BN;

    float acc[4][8][4];
#pragma unroll
    for (int mi = 0; mi < 4; mi++)
#pragma unroll
        for (int ni = 0; ni < 8; ni++)
#pragma unroll
            for (int r = 0; r < 4; r++) acc[mi][ni][r] = 0.0f;

    gemm_mainloop<TDIM>(Ah, Al, Wh, Wl, rowBase, colBase, sb, acc);

    const int lane = threadIdx.x & 31;
    const int warp = threadIdx.x >> 5;
    const int warpM = warp & 1, warpN = warp >> 1;
    const int g = lane >> 2, tg = lane & 3;

#pragma unroll
    for (int ni = 0; ni < 8; ni++) {
        const int n0 = colBase + warpN * 64 + ni * 8 + tg * 2;   // even
        const int n  = n0 >> 1;
        const float bmu = mu_b[n], bsg = sg_b[n];
        const float4* G4 = (const float4*)(G + n * 8);
        const float4 gA = G4[0], gB = G4[1];
#pragma unroll
        for (int mi = 0; mi < 4; mi++) {
#pragma unroll
            for (int h = 0; h < 2; h++) {
                const int m = rowBase + warpM * 64 + mi * 16 + g + h * 8;
                const float muv = tanhf(acc[mi][ni][2 * h + 0] + bmu);
                const float sgv = acc[mi][ni][2 * h + 1] + bsg;
                const float rs  = 1.0f / fmaf(sgv, sgv, 1e-8f);
                const float4* H4 = (const float4*)(g_H + ((size_t)m * TDIM + n) * 8);
                const float4 hA = H4[0], hB = H4[1];
                float d, s = 0.0f;
                d = gA.x - muv; s += __expf(-0.5f * d * d * rs) * hA.x;
                d = gA.y - muv; s += __expf(-0.5f * d * d * rs) * hA.y;
                d = gA.z - muv; s += __expf(-0.5f * d * d * rs) * hA.z;
                d = gA.w - muv; s += __expf(-0.5f * d * d * rs) * hA.w;
                d = gB.x - muv; s += __expf(-0.5f * d * d * rs) * hB.x;
                d = gB.y - muv; s += __expf(-0.5f * d * d * rs) * hB.y;
                d = gB.z - muv; s += __expf(-0.5f * d * d * rs) * hB.z;
                d = gB.w - muv; s += __expf(-0.5f * d * d * rs) * hB.w;
                Q[(size_t)m * TDIM + n] += s;
            }
        }
    }
}

// ---------------------------------------------------------------------------
// One-shot weight split (+ mu/sig interleave pack): fp32 -> bf16 hi/lo
// ---------------------------------------------------------------------------
__global__ __launch_bounds__(256) void wsplit_all(
    const float* __restrict__ mu_w, const float* __restrict__ sg_w,
    const float* __restrict__ a_w1, const float* __restrict__ a_w2,
    const float* __restrict__ m_w1, const float* __restrict__ m_w2)
{
    size_t i = (size_t)blockIdx.x * 256 + threadIdx.x;
    float v;
    if (i < AW1_OFF) {
        // packed musig: per attn block 1024x512 (2^19 elems)
        size_t a   = i >> 19;
        size_t rem = i & 524287;
        size_t r   = rem >> 9;          // interleaved row 0..1023
        size_t k   = rem & 511;
        size_t src = a * 262144 + (r >> 1) * 512 + k;
        v = (r & 1) ? sg_w[src] : mu_w[src];
    } else if (i < AW2_OFF) v = a_w1[i - AW1_OFF];
    else if (i < MW1_OFF)   v = a_w2[i - AW2_OFF];
    else if (i < MW2_OFF)   v = m_w1[i - MW1_OFF];
    else                    v = m_w2[i - MW2_OFF];
    __nv_bfloat16 h, l;
    split_bf16(v, h, l);
    g_wh[i] = h; g_wl[i] = l;
}

// ---------------------------------------------------------------------------
// Prep: H[b,n,k] = cos(omega[n,k,:].x[b,:] + phase[n,k])  (once)
//       Q0[b,t]  = silu(x[b,:].l1_w[t,:] + l1_b[t])
// ---------------------------------------------------------------------------
__global__ __launch_bounds__(256) void prep_kernel(
    const float* __restrict__ x, const float* __restrict__ omega,
    const float* __restrict__ phase, const float* __restrict__ l1_w,
    const float* __restrict__ l1_b)
{
    int idx = blockIdx.x * 256 + threadIdx.x;     // b*T + n
    int b = idx >> 9, n = idx & 511;
    float x0 = x[b * 2 + 0], x1 = x[b * 2 + 1];
    float out[8];
#pragma unroll
    for (int k = 0; k < 8; k++) {
        int nk = n * 8 + k;
        float arg = fmaf(omega[nk * 2 + 0], x0,
                    fmaf(omega[nk * 2 + 1], x1, phase[nk]));
        out[k] = cosf(arg);
    }
    float4* H4 = (float4*)(g_H + (size_t)idx * 8);
    H4[0] = make_float4(out[0], out[1], out[2], out[3]);
    H4[1] = make_float4(out[4], out[5], out[6], out[7]);

    float p = fmaf(x0, l1_w[n * 2 + 0], fmaf(x1, l1_w[n * 2 + 1], l1_b[n]));
    g_Q[idx] = silu_f(p);
}

// ---------------------------------------------------------------------------
// LayerNorm over T=512, one warp per row; outputs bf16 hi/lo split
// ---------------------------------------------------------------------------
__global__ __launch_bounds__(256) void ln_kernel(
    const float* __restrict__ X, const float* __restrict__ gam,
    const float* __restrict__ bet)
{
    int warp = threadIdx.x >> 5, lane = threadIdx.x & 31;
    int row = blockIdx.x * 8 + warp;
    const float4* xr = (const float4*)(X + (size_t)row * 512);
    float4 v[4];
    float s = 0.0f;
#pragma unroll
    for (int j = 0; j < 4; j++) {
        v[j] = xr[lane + j * 32];
        s += v[j].x + v[j].y + v[j].z + v[j].w;
    }
#pragma unroll
    for (int o = 16; o > 0; o >>= 1) s += __shfl_xor_sync(0xffffffffu, s, o);
    float m = s * (1.0f / 512.0f);
    float vs = 0.0f;
#pragma unroll
    for (int j = 0; j < 4; j++) {
        float dx = v[j].x - m, dy = v[j].y - m, dz = v[j].z - m, dw = v[j].w - m;
        vs += dx * dx + dy * dy + dz * dz + dw * dw;
    }
#pragma unroll
    for (int o = 16; o > 0; o >>= 1) vs += __shfl_xor_sync(0xffffffffu, vs, o);
    float inv = rsqrtf(vs * (1.0f / 512.0f) + 1e-5f);

    __nv_bfloat162* yh = (__nv_bfloat162*)(g_hh + (size_t)row * 512);
    __nv_bfloat162* yl = (__nv_bfloat162*)(g_hl + (size_t)row * 512);
    const float4* gr = (const float4*)gam;
    const float4* br = (const float4*)bet;
#pragma unroll
    for (int j = 0; j < 4; j++) {
        int c = lane + j * 32;
        float4 gg = gr[c], bb = br[c];
        float o0 = (v[j].x - m) * inv * gg.x + bb.x;
        float o1 = (v[j].y - m) * inv * gg.y + bb.y;
        float o2 = (v[j].z - m) * inv * gg.z + bb.z;
        float o3 = (v[j].w - m) * inv * gg.w + bb.w;
        __nv_bfloat16 h0, l0, h1, l1, h2, l2, h3, l3;
        split_bf16(o0, h0, l0); split_bf16(o1, h1, l1);
        split_bf16(o2, h2, l2); split_bf16(o3, h3, l3);
        yh[c * 2    ] = __halves2bfloat162(h0, h1);
        yh[c * 2 + 1] = __halves2bfloat162(h2, h3);
        yl[c * 2    ] = __halves2bfloat162(l0, l1);
        yl[c * 2 + 1] = __halves2bfloat162(l2, l3);
    }
}

// ---------------------------------------------------------------------------
// Readout: out[b] = sum_t silu(Q[b,t]) * ro_w[t] + ro_b
// ---------------------------------------------------------------------------
__global__ __launch_bounds__(256) void final_kernel(
    const float* __restrict__ ro_w, const float* __restrict__ ro_b,
    float* __restrict__ out)
{
    int warp = threadIdx.x >> 5, lane = threadIdx.x & 31;
    int row = blockIdx.x * 8 + warp;
    const float4* q4 = (const float4*)(g_Q + (size_t)row * 512);
    const float4* w4 = (const float4*)ro_w;
    float s = 0.0f;
#pragma unroll
    for (int j = 0; j < 4; j++) {
        int c = lane + j * 32;
        float4 q = q4[c], w = w4[c];
        s += silu_f(q.x) * w.x + silu_f(q.y) * w.y
           + silu_f(q.z) * w.z + silu_f(q.w) * w.w;
    }
#pragma unroll
    for (int o = 16; o > 0; o >>= 1) s += __shfl_xor_sync(0xffffffffu, s, o);
    if (lane == 0) out[row] = s + ro_b[0];
}

// ---------------------------------------------------------------------------
// Host launcher
// ---------------------------------------------------------------------------
extern "C" void kernel_launch(void* const* d_in, const int* in_sizes, int n_in,
                              void* d_out, int out_size)
{
    const float* x      = (const float*)d_in[0];
    const float* omega  = (const float*)d_in[1];
    const float* G      = (const float*)d_in[2];
    const float* phase  = (const float*)d_in[3];
    const float* l1_w   = (const float*)d_in[4];
    const float* l1_b   = (const float*)d_in[5];
    const float* mu_w   = (const float*)d_in[6];
    const float* mu_b   = (const float*)d_in[7];
    const float* sg_w   = (const float*)d_in[8];
    const float* sg_b   = (const float*)d_in[9];
    const float* alnqg  = (const float*)d_in[10];
    const float* alnqb  = (const float*)d_in[11];
    const float* alnfg  = (const float*)d_in[12];
    const float* alnfb  = (const float*)d_in[13];
    const float* a_w1   = (const float*)d_in[14];
    const float* a_b1   = (const float*)d_in[15];
    const float* a_w2   = (const float*)d_in[16];
    const float* a_b2   = (const float*)d_in[17];
    const float* mln_g  = (const float*)d_in[18];
    const float* mln_b  = (const float*)d_in[19];
    const float* m_w1   = (const float*)d_in[20];
    const float* m_b1   = (const float*)d_in[21];
    const float* m_w2   = (const float*)d_in[22];
    const float* m_b2   = (const float*)d_in[23];
    const float* ro_w   = (const float*)d_in[24];
    const float* ro_b   = (const float*)d_in[25];
    float* out = (float*)d_out;

    __nv_bfloat16* wh; __nv_bfloat16* wl;
    float* Q;
    __nv_bfloat16* hh; __nv_bfloat16* hl;
    __nv_bfloat16* th; __nv_bfloat16* tl;
    {
        void* p;
        cudaGetSymbolAddress(&p, g_wh); wh = (__nv_bfloat16*)p;
        cudaGetSymbolAddress(&p, g_wl); wl = (__nv_bfloat16*)p;
        cudaGetSymbolAddress(&p, g_Q);  Q  = (float*)p;
        cudaGetSymbolAddress(&p, g_hh); hh = (__nv_bfloat16*)p;
        cudaGetSymbolAddress(&p, g_hl); hl = (__nv_bfloat16*)p;
        cudaGetSymbolAddress(&p, g_th); th = (__nv_bfloat16*)p;
        cudaGetSymbolAddress(&p, g_tl); tl = (__nv_bfloat16*)p;
    }

    cudaFuncSetAttribute(gemm_musig,
                         cudaFuncAttributeMaxDynamicSharedMemorySize, SMEM_BYTES);
    cudaFuncSetAttribute(gemm_ffn1<TDIM, FDIM>,
                         cudaFuncAttributeMaxDynamicSharedMemorySize, SMEM_BYTES);
    cudaFuncSetAttribute(gemm_ffn2<FDIM, TDIM>,
                         cudaFuncAttributeMaxDynamicSharedMemorySize, SMEM_BYTES);

    const int ew_blocks = (BATCH * TDIM) / 256;   // 16384
    const dim3 g_ms(1024 / BN, BATCH / 128);      // (4, 64)
    const dim3 g_f1(FDIM / BN, BATCH / 128);      // (8, 64)
    const dim3 g_f2(TDIM / BN, BATCH / 128);      // (2, 64)

    wsplit_all<<<WTOTAL / 256, 256>>>(mu_w, sg_w, a_w1, a_w2, m_w1, m_w2);
    prep_kernel<<<ew_blocks, 256>>>(x, omega, phase, l1_w, l1_b);

    for (int i = 0; i < NATTN; i++) {
        const size_t wms = (size_t)i * 1024 * 512;
        const size_t wft = (size_t)i * FDIM * TDIM;
        ln_kernel<<<BATCH / 8, 256>>>(Q, alnqg + i * TDIM, alnqb + i * TDIM);
        gemm_musig<<<g_ms, NTHREADS, SMEM_BYTES>>>(
            hh, hl, wh + MS_OFF + wms, wl + MS_OFF + wms,
            mu_b + i * TDIM, sg_b + i * TDIM, G, Q);
        ln_kernel<<<BATCH / 8, 256>>>(Q, alnfg + i * TDIM, alnfb + i * TDIM);
        gemm_ffn1<TDIM, FDIM><<<g_f1, NTHREADS, SMEM_BYTES>>>(
            hh, hl, wh + AW1_OFF + wft, wl + AW1_OFF + wft,
            a_b1 + i * FDIM, th, tl);
        gemm_ffn2<FDIM, TDIM><<<g_f2, NTHREADS, SMEM_BYTES>>>(
            th, tl, wh + AW2_OFF + wft, wl + AW2_OFF + wft,
            a_b2 + i * TDIM, Q);
    }
    for (int i = 0; i < NMLP; i++) {
        const size_t wft = (size_t)i * FDIM * TDIM;
        ln_kernel<<<BATCH / 8, 256>>>(Q, mln_g + i * TDIM, mln_b + i * TDIM);
        gemm_ffn1<TDIM, FDIM><<<g_f1, NTHREADS, SMEM_BYTES>>>(
            hh, hl, wh + MW1_OFF + wft, wl + MW1_OFF + wft,
            m_b1 + i * FDIM, th, tl);
        gemm_ffn2<FDIM, TDIM><<<g_f2, NTHREADS, SMEM_BYTES>>>(
            th, tl, wh + MW2_OFF + wft, wl + MW2_OFF + wft,
            m_b2 + i * TDIM, Q);
    }
    final_kernel<<<BATCH / 8, 256>>>(ro_w, ro_b, out);
}

// round 13
// speedup vs baseline: 1.1828x; 1.1828x over previous
#include <cuda_runtime.h>
#include <cuda_bf16.h>
#include <cstdint>
#include <math.h>

// ---------------------------------------------------------------------------
// Problem constants
// ---------------------------------------------------------------------------
#define BATCH 8192
#define TDIM  512
#define FDIM  2048
#define NATTN 4
#define NMLP  2

// weight scratch layout (element offsets into g_wh / g_wl)
// [MS_OFF)  : packed mu/sig, per attn block 1024x512, rows interleaved
//             (even row r -> mu_w[r/2], odd row r -> sg_w[r/2])
#define MS_OFF  0
#define AW1_OFF 2097152
#define AW2_OFF 6291456
#define MW1_OFF 10485760
#define MW2_OFF 12582912
#define WTOTAL  14680064

#define NPERSIST 296   // 2 CTAs/SM x 148 SMs

// ---------------------------------------------------------------------------
// Device scratch (static — no allocation at launch time)
// ---------------------------------------------------------------------------
__device__ __nv_bfloat16 g_wh[WTOTAL];          // 29 MB  weight hi
__device__ __nv_bfloat16 g_wl[WTOTAL];          // 29 MB  weight lo
__device__ float         g_Q [BATCH * TDIM];    // 16 MB  residual stream
__device__ float         g_H [BATCH * TDIM * 8];// 128 MB RFF tokens (precomputed)
__device__ __nv_bfloat16 g_hh[BATCH * TDIM];    // LN output hi
__device__ __nv_bfloat16 g_hl[BATCH * TDIM];    // LN output lo
__device__ __nv_bfloat16 g_th[BATCH * FDIM];    // FFN mid hi
__device__ __nv_bfloat16 g_tl[BATCH * FDIM];    // FFN mid lo

// ---------------------------------------------------------------------------
// Helpers
// ---------------------------------------------------------------------------
__device__ __forceinline__ float silu_f(float x) {
    return x / (1.0f + __expf(-x));
}

__device__ __forceinline__ void split_bf16(float x, __nv_bfloat16& hi, __nv_bfloat16& lo) {
    hi = __float2bfloat16_rn(x);
    lo = __float2bfloat16_rn(x - __bfloat162float(hi));
}

__device__ __forceinline__ void mma_bf16(float* d, const uint32_t* a, const uint32_t* b) {
    asm volatile(
        "mma.sync.aligned.m16n8k16.row.col.f32.bf16.bf16.f32 "
        "{%0,%1,%2,%3}, {%4,%5,%6,%7}, {%8,%9}, {%0,%1,%2,%3};\n"
        : "+f"(d[0]), "+f"(d[1]), "+f"(d[2]), "+f"(d[3])
        : "r"(a[0]), "r"(a[1]), "r"(a[2]), "r"(a[3]), "r"(b[0]), "r"(b[1]));
}

__device__ __forceinline__ void cp16(uint32_t dst, const void* src) {
    asm volatile("cp.async.cg.shared.global [%0], [%1], 16;\n" :: "r"(dst), "l"(src));
}
__device__ __forceinline__ void cp_commit() {
    asm volatile("cp.async.commit_group;\n");
}
template<int N> __device__ __forceinline__ void cp_wait() {
    asm volatile("cp.async.wait_group %0;\n" :: "n"(N));
}

__device__ __forceinline__ void ldsm4(uint32_t& r0, uint32_t& r1, uint32_t& r2,
                                      uint32_t& r3, uint32_t addr) {
    asm volatile("ldmatrix.sync.aligned.m8n8.x4.shared.b16 {%0,%1,%2,%3}, [%4];\n"
                 : "=r"(r0), "=r"(r1), "=r"(r2), "=r"(r3) : "r"(addr));
}

// XOR-swizzled smem layout: per array, row r holds 32 bf16 = 64B = 4 chunks
// of 16B; logical chunk c lives at physical chunk c ^ ((r>>1)&3).
// ldmatrix phase (8 lanes = 8 consecutive rows, fixed c) and staging writes
// (warp = 8 rows x 4 chunks) both cover all 32 banks exactly: conflict-free.
__device__ __forceinline__ uint32_t swz(int r, int c) {
    return (uint32_t)(r * 64 + ((c ^ ((r >> 1) & 3)) * 16));
}

// ---------------------------------------------------------------------------
// GEMM mainloop (bf16x3 split): R10 config — 256 threads, 2 CTA/SM,
// warp grid 2m x 4n, warp tile 64x32 (best measured: 33.6% tensor) with
// XOR-swizzled unpadded layout, 3-stage cp.async ring, ONE __syncthreads
// per K-tile, prefetch distance 2.
//   acc += Ah*Wh + Ah*Wl + Al*Wh; term-major MMA order (reuse distance 4).
// Called repeatedly by persistent-CTA kernels; the __syncthreads at entry
// fences the previous tile's ldsm reads before buffer 0 is restaged.
// ---------------------------------------------------------------------------
#define ARR_BYTES   (128 * 64)         // 8192
#define STAGE_BYTES (4 * ARR_BYTES)    // 32768: Ahi, Alo, Whi, Wlo
#define NSTAGE 3
#define SMEM_BYTES  (NSTAGE * STAGE_BYTES)  // 98304
#define NTHREADS 256

template<int K>
__device__ __forceinline__ void gemm_mainloop(
    const __nv_bfloat16* __restrict__ Ah, const __nv_bfloat16* __restrict__ Al,
    const __nv_bfloat16* __restrict__ Wh, const __nv_bfloat16* __restrict__ Wl,
    int rowBase, int colBase, uint32_t sb, float acc[4][4][4])
{
    const int tid  = threadIdx.x;
    const int lane = tid & 31;
    const int warp = tid >> 5;
    const int warpM = warp & 1;
    const int warpN = warp >> 1;

    // staging: thread covers 16B chunks tid and tid+256 of each array
    const int r0s = tid >> 2,         q0s = tid & 3;
    const int r1s = (tid + 256) >> 2, q1s = tid & 3;   // same q, rows +64
    const uint32_t off0 = swz(r0s, q0s);
    const uint32_t off1 = swz(r1s, q1s);
    const __nv_bfloat16* a0 = Ah + (size_t)(rowBase + r0s) * K + q0s * 8;
    const __nv_bfloat16* l0 = Al + (size_t)(rowBase + r0s) * K + q0s * 8;
    const __nv_bfloat16* w0 = Wh + (size_t)(colBase + r0s) * K + q0s * 8;
    const __nv_bfloat16* v0 = Wl + (size_t)(colBase + r0s) * K + q0s * 8;
    const __nv_bfloat16* a1 = Ah + (size_t)(rowBase + r1s) * K + q1s * 8;
    const __nv_bfloat16* l1 = Al + (size_t)(rowBase + r1s) * K + q1s * 8;
    const __nv_bfloat16* w1 = Wh + (size_t)(colBase + r1s) * K + q1s * 8;
    const __nv_bfloat16* v1 = Wl + (size_t)(colBase + r1s) * K + q1s * 8;

    auto stage = [&](int s, int k0) {
        const uint32_t base = sb + s * STAGE_BYTES;
        cp16(base + 0 * ARR_BYTES + off0, a0 + k0);
        cp16(base + 1 * ARR_BYTES + off0, l0 + k0);
        cp16(base + 2 * ARR_BYTES + off0, w0 + k0);
        cp16(base + 3 * ARR_BYTES + off0, v0 + k0);
        cp16(base + 0 * ARR_BYTES + off1, a1 + k0);
        cp16(base + 1 * ARR_BYTES + off1, l1 + k0);
        cp16(base + 2 * ARR_BYTES + off1, w1 + k0);
        cp16(base + 3 * ARR_BYTES + off1, v1 + k0);
        cp_commit();
    };

    // fragment load offsets (precomputed; khalf = 16B column within k-chunk)
    const int ldrow = lane & 15;
    const int khalf = lane >> 4;                 // 0 or 1
    uint32_t offA[2][4], offB[2][2];
#pragma unroll
    for (int kc = 0; kc < 2; kc++) {
        const int c = kc * 2 + khalf;
#pragma unroll
        for (int mi = 0; mi < 4; mi++)
            offA[kc][mi] = swz(warpM * 64 + mi * 16 + ldrow, c);
#pragma unroll
        for (int p = 0; p < 2; p++)
            offB[kc][p]  = swz(warpN * 32 + p * 16 + ldrow, c);
    }

    // fence previous tile's smem reads (persistent loop) before restaging
    __syncthreads();

    const int nt = K / 32;                       // >= 16
    stage(0, 0);
    stage(1, 32);

    for (int it = 0; it < nt; it++) {
        if (it < nt - 1) cp_wait<1>(); else cp_wait<0>();
        __syncthreads();
        if (it + 2 < nt) stage((it + 2) % NSTAGE, (it + 2) * 32);

        const uint32_t base = sb + (it % NSTAGE) * STAGE_BYTES;
#pragma unroll
        for (int kc = 0; kc < 2; kc++) {
            uint32_t bhi[4][2], blo[4][2];
#pragma unroll
            for (int p = 0; p < 2; p++) {
                uint32_t r0, r1, r2, r3;
                ldsm4(r0, r1, r2, r3, base + 2 * ARR_BYTES + offB[kc][p]);
                bhi[2 * p][0] = r0; bhi[2 * p + 1][0] = r1;
                bhi[2 * p][1] = r2; bhi[2 * p + 1][1] = r3;
                ldsm4(r0, r1, r2, r3, base + 3 * ARR_BYTES + offB[kc][p]);
                blo[2 * p][0] = r0; blo[2 * p + 1][0] = r1;
                blo[2 * p][1] = r2; blo[2 * p + 1][1] = r3;
            }
#pragma unroll
            for (int mi = 0; mi < 4; mi++) {
                uint32_t ah[4], al[4];
                ldsm4(ah[0], ah[1], ah[2], ah[3], base + 0 * ARR_BYTES + offA[kc][mi]);
                ldsm4(al[0], al[1], al[2], al[3], base + 1 * ARR_BYTES + offA[kc][mi]);
                // term-major: 4 independent MMAs between acc reuses
#pragma unroll
                for (int ni = 0; ni < 4; ni++) mma_bf16(acc[mi][ni], ah, bhi[ni]);
#pragma unroll
                for (int ni = 0; ni < 4; ni++) mma_bf16(acc[mi][ni], ah, blo[ni]);
#pragma unroll
                for (int ni = 0; ni < 4; ni++) mma_bf16(acc[mi][ni], al, bhi[ni]);
            }
        }
    }
}

// ---------------------------------------------------------------------------
// FFN first GEMM (persistent): t = silu(h @ W1^T + b1), bf16 hi/lo output
// ---------------------------------------------------------------------------
template<int K, int N>
__global__ __launch_bounds__(NTHREADS, 2) void gemm_ffn1(
    const __nv_bfloat16* __restrict__ Ah, const __nv_bfloat16* __restrict__ Al,
    const __nv_bfloat16* __restrict__ Wh, const __nv_bfloat16* __restrict__ Wl,
    const float* __restrict__ bias,
    __nv_bfloat16* __restrict__ Ch, __nv_bfloat16* __restrict__ Cl)
{
    extern __shared__ __align__(128) uint32_t smem[];
    const uint32_t sb = (uint32_t)__cvta_generic_to_shared(smem);
    const int NX = N / 128;
    const int NT = (BATCH / 128) * NX;

    const int lane = threadIdx.x & 31;
    const int warp = threadIdx.x >> 5;
    const int warpM = warp & 1, warpN = warp >> 1;
    const int g = lane >> 2, tg = lane & 3;

    for (int t = blockIdx.x; t < NT; t += gridDim.x) {
        const int rowBase = (t / NX) * 128;
        const int colBase = (t % NX) * 128;

        float acc[4][4][4];
#pragma unroll
        for (int mi = 0; mi < 4; mi++)
#pragma unroll
            for (int ni = 0; ni < 4; ni++)
#pragma unroll
                for (int r = 0; r < 4; r++) acc[mi][ni][r] = 0.0f;

        gemm_mainloop<K>(Ah, Al, Wh, Wl, rowBase, colBase, sb, acc);

#pragma unroll
        for (int mi = 0; mi < 4; mi++) {
#pragma unroll
            for (int ni = 0; ni < 4; ni++) {
                int m0 = rowBase + warpM * 64 + mi * 16 + g;
                int n0 = colBase + warpN * 32 + ni * 8 + tg * 2;
                float bn0 = bias[n0], bn1 = bias[n0 + 1];
#pragma unroll
                for (int h = 0; h < 2; h++) {
                    int m = m0 + h * 8;
                    float u0 = silu_f(acc[mi][ni][2 * h + 0] + bn0);
                    float u1 = silu_f(acc[mi][ni][2 * h + 1] + bn1);
                    size_t idx = (size_t)m * N + n0;
                    __nv_bfloat16 h0, l0, h1, l1;
                    split_bf16(u0, h0, l0);
                    split_bf16(u1, h1, l1);
                    *(__nv_bfloat162*)(Ch + idx) = __halves2bfloat162(h0, h1);
                    *(__nv_bfloat162*)(Cl + idx) = __halves2bfloat162(l0, l1);
                }
            }
        }
    }
}

// ---------------------------------------------------------------------------
// FFN second GEMM (persistent): Q += t @ W2^T + b2  (residual, in place)
// ---------------------------------------------------------------------------
template<int K, int N>
__global__ __launch_bounds__(NTHREADS, 2) void gemm_ffn2(
    const __nv_bfloat16* __restrict__ Ah, const __nv_bfloat16* __restrict__ Al,
    const __nv_bfloat16* __restrict__ Wh, const __nv_bfloat16* __restrict__ Wl,
    const float* __restrict__ bias, float* __restrict__ C)
{
    extern __shared__ __align__(128) uint32_t smem[];
    const uint32_t sb = (uint32_t)__cvta_generic_to_shared(smem);
    const int NX = N / 128;
    const int NT = (BATCH / 128) * NX;

    const int lane = threadIdx.x & 31;
    const int warp = threadIdx.x >> 5;
    const int warpM = warp & 1, warpN = warp >> 1;
    const int g = lane >> 2, tg = lane & 3;

    for (int t = blockIdx.x; t < NT; t += gridDim.x) {
        const int rowBase = (t / NX) * 128;
        const int colBase = (t % NX) * 128;

        float acc[4][4][4];
#pragma unroll
        for (int mi = 0; mi < 4; mi++)
#pragma unroll
            for (int ni = 0; ni < 4; ni++)
#pragma unroll
                for (int r = 0; r < 4; r++) acc[mi][ni][r] = 0.0f;

        gemm_mainloop<K>(Ah, Al, Wh, Wl, rowBase, colBase, sb, acc);

#pragma unroll
        for (int mi = 0; mi < 4; mi++) {
#pragma unroll
            for (int ni = 0; ni < 4; ni++) {
                int m0 = rowBase + warpM * 64 + mi * 16 + g;
                int n0 = colBase + warpN * 32 + ni * 8 + tg * 2;
                float bn0 = bias[n0], bn1 = bias[n0 + 1];
#pragma unroll
                for (int h = 0; h < 2; h++) {
                    int m = m0 + h * 8;
                    size_t idx = (size_t)m * N + n0;
                    C[idx]     = acc[mi][ni][2 * h + 0] + bn0 + C[idx];
                    C[idx + 1] = acc[mi][ni][2 * h + 1] + bn1 + C[idx + 1];
                }
            }
        }
    }
}

// ---------------------------------------------------------------------------
// Fused mu/sig GEMM + attention gather (persistent; H precomputed in g_H).
// W is the packed interleaved [1024, 512] matrix (even rows mu, odd rows sig)
// so each epilogue pair (n0, n0+1) = (mu, sig) for token n = n0/2. Epilogue:
//   mu = tanh(v0 + mu_b[n]); sg = v1 + sg_b[n]
//   Q[m,n] += sum_k exp(-0.5 (G[n,k]-mu)^2 / (sg^2+eps)) * H[m,n,k]
// ---------------------------------------------------------------------------
__global__ __launch_bounds__(NTHREADS, 2) void gemm_musig(
    const __nv_bfloat16* __restrict__ Ah, const __nv_bfloat16* __restrict__ Al,
    const __nv_bfloat16* __restrict__ Wh, const __nv_bfloat16* __restrict__ Wl,
    const float* __restrict__ mu_b, const float* __restrict__ sg_b,
    const float* __restrict__ G, float* __restrict__ Q)
{
    extern __shared__ __align__(128) uint32_t smem[];
    const uint32_t sb = (uint32_t)__cvta_generic_to_shared(smem);
    const int NX = 1024 / 128;                   // 8
    const int NT = (BATCH / 128) * NX;           // 512

    const int lane = threadIdx.x & 31;
    const int warp = threadIdx.x >> 5;
    const int warpM = warp & 1, warpN = warp >> 1;
    const int g = lane >> 2, tg = lane & 3;

    for (int t = blockIdx.x; t < NT; t += gridDim.x) {
        const int rowBase = (t / NX) * 128;
        const int colBase = (t % NX) * 128;

        float acc[4][4][4];
#pragma unroll
        for (int mi = 0; mi < 4; mi++)
#pragma unroll
            for (int ni = 0; ni < 4; ni++)
#pragma unroll
                for (int r = 0; r < 4; r++) acc[mi][ni][r] = 0.0f;

        gemm_mainloop<TDIM>(Ah, Al, Wh, Wl, rowBase, colBase, sb, acc);

#pragma unroll
        for (int ni = 0; ni < 4; ni++) {
            const int n0 = colBase + warpN * 32 + ni * 8 + tg * 2;   // even
            const int n  = n0 >> 1;
            const float bmu = mu_b[n], bsg = sg_b[n];
            const float4* G4 = (const float4*)(G + n * 8);
            const float4 gA = G4[0], gB = G4[1];
#pragma unroll
            for (int mi = 0; mi < 4; mi++) {
#pragma unroll
                for (int h = 0; h < 2; h++) {
                    const int m = rowBase + warpM * 64 + mi * 16 + g + h * 8;
                    const float muv = tanhf(acc[mi][ni][2 * h + 0] + bmu);
                    const float sgv = acc[mi][ni][2 * h + 1] + bsg;
                    const float rs  = 1.0f / fmaf(sgv, sgv, 1e-8f);
                    const float4* H4 = (const float4*)(g_H + ((size_t)m * TDIM + n) * 8);
                    const float4 hA = H4[0], hB = H4[1];
                    float d, s = 0.0f;
                    d = gA.x - muv; s += __expf(-0.5f * d * d * rs) * hA.x;
                    d = gA.y - muv; s += __expf(-0.5f * d * d * rs) * hA.y;
                    d = gA.z - muv; s += __expf(-0.5f * d * d * rs) * hA.z;
                    d = gA.w - muv; s += __expf(-0.5f * d * d * rs) * hA.w;
                    d = gB.x - muv; s += __expf(-0.5f * d * d * rs) * hB.x;
                    d = gB.y - muv; s += __expf(-0.5f * d * d * rs) * hB.y;
                    d = gB.z - muv; s += __expf(-0.5f * d * d * rs) * hB.z;
                    d = gB.w - muv; s += __expf(-0.5f * d * d * rs) * hB.w;
                    Q[(size_t)m * TDIM + n] += s;
                }
            }
        }
    }
}

// ---------------------------------------------------------------------------
// One-shot weight split (+ mu/sig interleave pack): fp32 -> bf16 hi/lo
// ---------------------------------------------------------------------------
__global__ __launch_bounds__(256) void wsplit_all(
    const float* __restrict__ mu_w, const float* __restrict__ sg_w,
    const float* __restrict__ a_w1, const float* __restrict__ a_w2,
    const float* __restrict__ m_w1, const float* __restrict__ m_w2)
{
    size_t i = (size_t)blockIdx.x * 256 + threadIdx.x;
    float v;
    if (i < AW1_OFF) {
        // packed musig: per attn block 1024x512 (2^19 elems)
        size_t a   = i >> 19;
        size_t rem = i & 524287;
        size_t r   = rem >> 9;          // interleaved row 0..1023
        size_t k   = rem & 511;
        size_t src = a * 262144 + (r >> 1) * 512 + k;
        v = (r & 1) ? sg_w[src] : mu_w[src];
    } else if (i < AW2_OFF) v = a_w1[i - AW1_OFF];
    else if (i < MW1_OFF)   v = a_w2[i - AW2_OFF];
    else if (i < MW2_OFF)   v = m_w1[i - MW1_OFF];
    else                    v = m_w2[i - MW2_OFF];
    __nv_bfloat16 h, l;
    split_bf16(v, h, l);
    g_wh[i] = h; g_wl[i] = l;
}

// ---------------------------------------------------------------------------
// Prep: H[b,n,k] = cos(omega[n,k,:].x[b,:] + phase[n,k])  (once)
//       Q0[b,t]  = silu(x[b,:].l1_w[t,:] + l1_b[t])
// ---------------------------------------------------------------------------
__global__ __launch_bounds__(256) void prep_kernel(
    const float* __restrict__ x, const float* __restrict__ omega,
    const float* __restrict__ phase, const float* __restrict__ l1_w,
    const float* __restrict__ l1_b)
{
    int idx = blockIdx.x * 256 + threadIdx.x;     // b*T + n
    int b = idx >> 9, n = idx & 511;
    float x0 = x[b * 2 + 0], x1 = x[b * 2 + 1];
    float out[8];
#pragma unroll
    for (int k = 0; k < 8; k++) {
        int nk = n * 8 + k;
        float arg = fmaf(omega[nk * 2 + 0], x0,
                    fmaf(omega[nk * 2 + 1], x1, phase[nk]));
        out[k] = cosf(arg);
    }
    float4* H4 = (float4*)(g_H + (size_t)idx * 8);
    H4[0] = make_float4(out[0], out[1], out[2], out[3]);
    H4[1] = make_float4(out[4], out[5], out[6], out[7]);

    float p = fmaf(x0, l1_w[n * 2 + 0], fmaf(x1, l1_w[n * 2 + 1], l1_b[n]));
    g_Q[idx] = silu_f(p);
}

// ---------------------------------------------------------------------------
// LayerNorm over T=512, one warp per row; outputs bf16 hi/lo split
// ---------------------------------------------------------------------------
__global__ __launch_bounds__(256) void ln_kernel(
    const float* __restrict__ X, const float* __restrict__ gam,
    const float* __restrict__ bet)
{
    int warp = threadIdx.x >> 5, lane = threadIdx.x & 31;
    int row = blockIdx.x * 8 + warp;
    const float4* xr = (const float4*)(X + (size_t)row * 512);
    float4 v[4];
    float s = 0.0f;
#pragma unroll
    for (int j = 0; j < 4; j++) {
        v[j] = xr[lane + j * 32];
        s += v[j].x + v[j].y + v[j].z + v[j].w;
    }
#pragma unroll
    for (int o = 16; o > 0; o >>= 1) s += __shfl_xor_sync(0xffffffffu, s, o);
    float m = s * (1.0f / 512.0f);
    float vs = 0.0f;
#pragma unroll
    for (int j = 0; j < 4; j++) {
        float dx = v[j].x - m, dy = v[j].y - m, dz = v[j].z - m, dw = v[j].w - m;
        vs += dx * dx + dy * dy + dz * dz + dw * dw;
    }
#pragma unroll
    for (int o = 16; o > 0; o >>= 1) vs += __shfl_xor_sync(0xffffffffu, vs, o);
    float inv = rsqrtf(vs * (1.0f / 512.0f) + 1e-5f);

    __nv_bfloat162* yh = (__nv_bfloat162*)(g_hh + (size_t)row * 512);
    __nv_bfloat162* yl = (__nv_bfloat162*)(g_hl + (size_t)row * 512);
    const float4* gr = (const float4*)gam;
    const float4* br = (const float4*)bet;
#pragma unroll
    for (int j = 0; j < 4; j++) {
        int c = lane + j * 32;
        float4 gg = gr[c], bb = br[c];
        float o0 = (v[j].x - m) * inv * gg.x + bb.x;
        float o1 = (v[j].y - m) * inv * gg.y + bb.y;
        float o2 = (v[j].z - m) * inv * gg.z + bb.z;
        float o3 = (v[j].w - m) * inv * gg.w + bb.w;
        __nv_bfloat16 h0, l0, h1, l1, h2, l2, h3, l3;
        split_bf16(o0, h0, l0); split_bf16(o1, h1, l1);
        split_bf16(o2, h2, l2); split_bf16(o3, h3, l3);
        yh[c * 2    ] = __halves2bfloat162(h0, h1);
        yh[c * 2 + 1] = __halves2bfloat162(h2, h3);
        yl[c * 2    ] = __halves2bfloat162(l0, l1);
        yl[c * 2 + 1] = __halves2bfloat162(l2, l3);
    }
}

// ---------------------------------------------------------------------------
// Readout: out[b] = sum_t silu(Q[b,t]) * ro_w[t] + ro_b
// ---------------------------------------------------------------------------
__global__ __launch_bounds__(256) void final_kernel(
    const float* __restrict__ ro_w, const float* __restrict__ ro_b,
    float* __restrict__ out)
{
    int warp = threadIdx.x >> 5, lane = threadIdx.x & 31;
    int row = blockIdx.x * 8 + warp;
    const float4* q4 = (const float4*)(g_Q + (size_t)row * 512);
    const float4* w4 = (const float4*)ro_w;
    float s = 0.0f;
#pragma unroll
    for (int j = 0; j < 4; j++) {
        int c = lane + j * 32;
        float4 q = q4[c], w = w4[c];
        s += silu_f(q.x) * w.x + silu_f(q.y) * w.y
           + silu_f(q.z) * w.z + silu_f(q.w) * w.w;
    }
#pragma unroll
    for (int o = 16; o > 0; o >>= 1) s += __shfl_xor_sync(0xffffffffu, s, o);
    if (lane == 0) out[row] = s + ro_b[0];
}

// ---------------------------------------------------------------------------
// Host launcher
// ---------------------------------------------------------------------------
extern "C" void kernel_launch(void* const* d_in, const int* in_sizes, int n_in,
                              void* d_out, int out_size)
{
    const float* x      = (const float*)d_in[0];
    const float* omega  = (const float*)d_in[1];
    const float* G      = (const float*)d_in[2];
    const float* phase  = (const float*)d_in[3];
    const float* l1_w   = (const float*)d_in[4];
    const float* l1_b   = (const float*)d_in[5];
    const float* mu_w   = (const float*)d_in[6];
    const float* mu_b   = (const float*)d_in[7];
    const float* sg_w   = (const float*)d_in[8];
    const float* sg_b   = (const float*)d_in[9];
    const float* alnqg  = (const float*)d_in[10];
    const float* alnqb  = (const float*)d_in[11];
    const float* alnfg  = (const float*)d_in[12];
    const float* alnfb  = (const float*)d_in[13];
    const float* a_w1   = (const float*)d_in[14];
    const float* a_b1   = (const float*)d_in[15];
    const float* a_w2   = (const float*)d_in[16];
    const float* a_b2   = (const float*)d_in[17];
    const float* mln_g  = (const float*)d_in[18];
    const float* mln_b  = (const float*)d_in[19];
    const float* m_w1   = (const float*)d_in[20];
    const float* m_b1   = (const float*)d_in[21];
    const float* m_w2   = (const float*)d_in[22];
    const float* m_b2   = (const float*)d_in[23];
    const float* ro_w   = (const float*)d_in[24];
    const float* ro_b   = (const float*)d_in[25];
    float* out = (float*)d_out;

    __nv_bfloat16* wh; __nv_bfloat16* wl;
    float* Q;
    __nv_bfloat16* hh; __nv_bfloat16* hl;
    __nv_bfloat16* th; __nv_bfloat16* tl;
    {
        void* p;
        cudaGetSymbolAddress(&p, g_wh); wh = (__nv_bfloat16*)p;
        cudaGetSymbolAddress(&p, g_wl); wl = (__nv_bfloat16*)p;
        cudaGetSymbolAddress(&p, g_Q);  Q  = (float*)p;
        cudaGetSymbolAddress(&p, g_hh); hh = (__nv_bfloat16*)p;
        cudaGetSymbolAddress(&p, g_hl); hl = (__nv_bfloat16*)p;
        cudaGetSymbolAddress(&p, g_th); th = (__nv_bfloat16*)p;
        cudaGetSymbolAddress(&p, g_tl); tl = (__nv_bfloat16*)p;
    }

    cudaFuncSetAttribute(gemm_musig,
                         cudaFuncAttributeMaxDynamicSharedMemorySize, SMEM_BYTES);
    cudaFuncSetAttribute(gemm_ffn1<TDIM, FDIM>,
                         cudaFuncAttributeMaxDynamicSharedMemorySize, SMEM_BYTES);
    cudaFuncSetAttribute(gemm_ffn2<FDIM, TDIM>,
                         cudaFuncAttributeMaxDynamicSharedMemorySize, SMEM_BYTES);

    const int ew_blocks = (BATCH * TDIM) / 256;   // 16384
    const dim3 g_pers(NPERSIST);                  // persistent CTA grid

    wsplit_all<<<WTOTAL / 256, 256>>>(mu_w, sg_w, a_w1, a_w2, m_w1, m_w2);
    prep_kernel<<<ew_blocks, 256>>>(x, omega, phase, l1_w, l1_b);

    for (int i = 0; i < NATTN; i++) {
        const size_t wms = (size_t)i * 1024 * 512;
        const size_t wft = (size_t)i * FDIM * TDIM;
        ln_kernel<<<BATCH / 8, 256>>>(Q, alnqg + i * TDIM, alnqb + i * TDIM);
        gemm_musig<<<g_pers, NTHREADS, SMEM_BYTES>>>(
            hh, hl, wh + MS_OFF + wms, wl + MS_OFF + wms,
            mu_b + i * TDIM, sg_b + i * TDIM, G, Q);
        ln_kernel<<<BATCH / 8, 256>>>(Q, alnfg + i * TDIM, alnfb + i * TDIM);
        gemm_ffn1<TDIM, FDIM><<<g_pers, NTHREADS, SMEM_BYTES>>>(
            hh, hl, wh + AW1_OFF + wft, wl + AW1_OFF + wft,
            a_b1 + i * FDIM, th, tl);
        gemm_ffn2<FDIM, TDIM><<<g_pers, NTHREADS, SMEM_BYTES>>>(
            th, tl, wh + AW2_OFF + wft, wl + AW2_OFF + wft,
            a_b2 + i * TDIM, Q);
    }
    for (int i = 0; i < NMLP; i++) {
        const size_t wft = (size_t)i * FDIM * TDIM;
        ln_kernel<<<BATCH / 8, 256>>>(Q, mln_g + i * TDIM, mln_b + i * TDIM);
        gemm_ffn1<TDIM, FDIM><<<g_pers, NTHREADS, SMEM_BYTES>>>(
            hh, hl, wh + MW1_OFF + wft, wl + MW1_OFF + wft,
            m_b1 + i * FDIM, th, tl);
        gemm_ffn2<FDIM, TDIM><<<g_pers, NTHREADS, SMEM_BYTES>>>(
            th, tl, wh + MW2_OFF + wft, wl + MW2_OFF + wft,
            m_b2 + i * TDIM, Q);
    }
    final_kernel<<<BATCH / 8, 256>>>(ro_w, ro_b, out);
}

// round 15
// speedup vs baseline: 1.5806x; 1.3363x over previous
#include <cuda_runtime.h>
#include <cuda_bf16.h>
#include <cuda_fp16.h>
#include <cstdint>
#include <math.h>

// ---------------------------------------------------------------------------
// Problem constants
// ---------------------------------------------------------------------------
#define BATCH 8192
#define TDIM  512
#define FDIM  2048
#define NATTN 4
#define NMLP  2

// musig (bf16) weight scratch: packed mu/sig, per attn block 1024x512,
// rows interleaved (even row r -> mu_w[r/2], odd row r -> sg_w[r/2])
#define MS_TOTAL 2097152
// FFN (fp16) weight scratch offsets
#define FAW1_OFF 0
#define FAW2_OFF 4194304
#define FMW1_OFF 8388608
#define FMW2_OFF 10485760
#define FW_TOTAL 12582912

// ---------------------------------------------------------------------------
// Device scratch (static — no allocation at launch time)
// ---------------------------------------------------------------------------
__device__ __nv_bfloat16 g_wh [MS_TOTAL];        // musig weight hi (bf16)
__device__ __nv_bfloat16 g_wl [MS_TOTAL];        // musig weight lo (bf16)
__device__ __half        g_fwh[FW_TOTAL];        // FFN weight hi (fp16)
__device__ __half        g_fwl[FW_TOTAL];        // FFN weight lo (fp16)
__device__ float         g_Q  [BATCH * TDIM];    // residual stream
__device__ float         g_H  [BATCH * TDIM * 8];// RFF tokens (precomputed)
__device__ __nv_bfloat16 g_hh [BATCH * TDIM];    // LN out hi (musig input)
__device__ __nv_bfloat16 g_hl [BATCH * TDIM];    // LN out lo (musig input)
__device__ __half        g_hf [BATCH * TDIM];    // LN out fp16 (FFN input)
__device__ __half        g_tf [BATCH * FDIM];    // FFN mid fp16

// ---------------------------------------------------------------------------
// Helpers
// ---------------------------------------------------------------------------
__device__ __forceinline__ float silu_f(float x) {
    return x / (1.0f + __expf(-x));
}

__device__ __forceinline__ void split_bf16(float x, __nv_bfloat16& hi, __nv_bfloat16& lo) {
    hi = __float2bfloat16_rn(x);
    lo = __float2bfloat16_rn(x - __bfloat162float(hi));
}

__device__ __forceinline__ void split_fp16(float x, __half& hi, __half& lo) {
    hi = __float2half_rn(x);
    lo = __float2half_rn(x - __half2float(hi));
}

__device__ __forceinline__ void mma_bf16(float* d, const uint32_t* a, const uint32_t* b) {
    asm volatile(
        "mma.sync.aligned.m16n8k16.row.col.f32.bf16.bf16.f32 "
        "{%0,%1,%2,%3}, {%4,%5,%6,%7}, {%8,%9}, {%0,%1,%2,%3};\n"
        : "+f"(d[0]), "+f"(d[1]), "+f"(d[2]), "+f"(d[3])
        : "r"(a[0]), "r"(a[1]), "r"(a[2]), "r"(a[3]), "r"(b[0]), "r"(b[1]));
}

__device__ __forceinline__ void mma_fp16(float* d, const uint32_t* a, const uint32_t* b) {
    asm volatile(
        "mma.sync.aligned.m16n8k16.row.col.f32.f16.f16.f32 "
        "{%0,%1,%2,%3}, {%4,%5,%6,%7}, {%8,%9}, {%0,%1,%2,%3};\n"
        : "+f"(d[0]), "+f"(d[1]), "+f"(d[2]), "+f"(d[3])
        : "r"(a[0]), "r"(a[1]), "r"(a[2]), "r"(a[3]), "r"(b[0]), "r"(b[1]));
}

__device__ __forceinline__ void cp16(uint32_t dst, const void* src) {
    asm volatile("cp.async.cg.shared.global [%0], [%1], 16;\n" :: "r"(dst), "l"(src));
}
__device__ __forceinline__ void cp_commit() {
    asm volatile("cp.async.commit_group;\n");
}
template<int N> __device__ __forceinline__ void cp_wait() {
    asm volatile("cp.async.wait_group %0;\n" :: "n"(N));
}

__device__ __forceinline__ void ldsm4(uint32_t& r0, uint32_t& r1, uint32_t& r2,
                                      uint32_t& r3, uint32_t addr) {
    asm volatile("ldmatrix.sync.aligned.m8n8.x4.shared.b16 {%0,%1,%2,%3}, [%4];\n"
                 : "=r"(r0), "=r"(r1), "=r"(r2), "=r"(r3) : "r"(addr));
}

// XOR-swizzled smem layout: per array, row r holds 32 elems(16b) = 64B =
// 4 chunks of 16B; logical chunk c lives at physical chunk c ^ ((r>>1)&3).
// Both the 8-row ldmatrix phases and the staging writes cover all 32 banks
// exactly: conflict-free.
__device__ __forceinline__ uint32_t swz(int r, int c) {
    return (uint32_t)(r * 64 + ((c ^ ((r >> 1) & 3)) * 16));
}

#define ARR_BYTES 8192                 // 128 rows x 64 B
#define NTHREADS 256

// ---------------------------------------------------------------------------
// bf16x3 split mainloop (musig only): R10 config — 256 threads, 2 CTA/SM,
// warp grid 2m x 4n, warp tile 64x32, 3-stage cp.async ring, one
// __syncthreads per K-tile, prefetch distance 2.
//   acc += Ah*Wh + Ah*Wl + Al*Wh; term-major (reuse distance 4).
// ---------------------------------------------------------------------------
#define B_STAGE (4 * ARR_BYTES)        // 32768: Ahi, Alo, Whi, Wlo
#define B_SMEM  (3 * B_STAGE)          // 98304

template<int K>
__device__ __forceinline__ void mainloop_bf16(
    const __nv_bfloat16* __restrict__ Ah, const __nv_bfloat16* __restrict__ Al,
    const __nv_bfloat16* __restrict__ Wh, const __nv_bfloat16* __restrict__ Wl,
    int rowBase, int colBase, uint32_t sb, float acc[4][4][4])
{
    const int tid  = threadIdx.x;
    const int lane = tid & 31;
    const int warp = tid >> 5;
    const int warpM = warp & 1;
    const int warpN = warp >> 1;

    const int r0s = tid >> 2,         q0s = tid & 3;
    const int r1s = (tid + 256) >> 2;
    const uint32_t off0 = swz(r0s, q0s);
    const uint32_t off1 = swz(r1s, q0s);
    const __nv_bfloat16* a0 = Ah + (size_t)(rowBase + r0s) * K + q0s * 8;
    const __nv_bfloat16* l0 = Al + (size_t)(rowBase + r0s) * K + q0s * 8;
    const __nv_bfloat16* w0 = Wh + (size_t)(colBase + r0s) * K + q0s * 8;
    const __nv_bfloat16* v0 = Wl + (size_t)(colBase + r0s) * K + q0s * 8;
    const __nv_bfloat16* a1 = Ah + (size_t)(rowBase + r1s) * K + q0s * 8;
    const __nv_bfloat16* l1 = Al + (size_t)(rowBase + r1s) * K + q0s * 8;
    const __nv_bfloat16* w1 = Wh + (size_t)(colBase + r1s) * K + q0s * 8;
    const __nv_bfloat16* v1 = Wl + (size_t)(colBase + r1s) * K + q0s * 8;

    auto stage = [&](int s, int k0) {
        const uint32_t base = sb + s * B_STAGE;
        cp16(base + 0 * ARR_BYTES + off0, a0 + k0);
        cp16(base + 1 * ARR_BYTES + off0, l0 + k0);
        cp16(base + 2 * ARR_BYTES + off0, w0 + k0);
        cp16(base + 3 * ARR_BYTES + off0, v0 + k0);
        cp16(base + 0 * ARR_BYTES + off1, a1 + k0);
        cp16(base + 1 * ARR_BYTES + off1, l1 + k0);
        cp16(base + 2 * ARR_BYTES + off1, w1 + k0);
        cp16(base + 3 * ARR_BYTES + off1, v1 + k0);
        cp_commit();
    };

    const int ldrow = lane & 15;
    const int khalf = lane >> 4;
    uint32_t offA[2][4], offB[2][2];
#pragma unroll
    for (int kc = 0; kc < 2; kc++) {
        const int c = kc * 2 + khalf;
#pragma unroll
        for (int mi = 0; mi < 4; mi++)
            offA[kc][mi] = swz(warpM * 64 + mi * 16 + ldrow, c);
#pragma unroll
        for (int p = 0; p < 2; p++)
            offB[kc][p]  = swz(warpN * 32 + p * 16 + ldrow, c);
    }

    const int nt = K / 32;
    stage(0, 0);
    stage(1, 32);

    for (int it = 0; it < nt; it++) {
        if (it < nt - 1) cp_wait<1>(); else cp_wait<0>();
        __syncthreads();
        if (it + 2 < nt) stage((it + 2) % 3, (it + 2) * 32);

        const uint32_t base = sb + (it % 3) * B_STAGE;
#pragma unroll
        for (int kc = 0; kc < 2; kc++) {
            uint32_t bhi[4][2], blo[4][2];
#pragma unroll
            for (int p = 0; p < 2; p++) {
                uint32_t r0, r1, r2, r3;
                ldsm4(r0, r1, r2, r3, base + 2 * ARR_BYTES + offB[kc][p]);
                bhi[2 * p][0] = r0; bhi[2 * p + 1][0] = r1;
                bhi[2 * p][1] = r2; bhi[2 * p + 1][1] = r3;
                ldsm4(r0, r1, r2, r3, base + 3 * ARR_BYTES + offB[kc][p]);
                blo[2 * p][0] = r0; blo[2 * p + 1][0] = r1;
                blo[2 * p][1] = r2; blo[2 * p + 1][1] = r3;
            }
#pragma unroll
            for (int mi = 0; mi < 4; mi++) {
                uint32_t ah[4], al[4];
                ldsm4(ah[0], ah[1], ah[2], ah[3], base + 0 * ARR_BYTES + offA[kc][mi]);
                ldsm4(al[0], al[1], al[2], al[3], base + 1 * ARR_BYTES + offA[kc][mi]);
#pragma unroll
                for (int ni = 0; ni < 4; ni++) mma_bf16(acc[mi][ni], ah, bhi[ni]);
#pragma unroll
                for (int ni = 0; ni < 4; ni++) mma_bf16(acc[mi][ni], ah, blo[ni]);
#pragma unroll
                for (int ni = 0; ni < 4; ni++) mma_bf16(acc[mi][ni], al, bhi[ni]);
            }
        }
    }
}

// ---------------------------------------------------------------------------
// fp16x2 split mainloop (FFN): activations single fp16, weights fp16 hi/lo
// (pre-split, exact to 2^-24). acc += A*Wh + A*Wl — 2 MMAs per term pair,
// 88KB smem traffic per tile vs 128KB for bf16x3. Same ring/barrier scheme.
// ---------------------------------------------------------------------------
#define F_STAGE (3 * ARR_BYTES)        // 24576: A, Wh, Wl
#define F_SMEM  (3 * F_STAGE)          // 73728

template<int K>
__device__ __forceinline__ void mainloop_fp16(
    const __half* __restrict__ A,
    const __half* __restrict__ Wh, const __half* __restrict__ Wl,
    int rowBase, int colBase, uint32_t sb, float acc[4][4][4])
{
    const int tid  = threadIdx.x;
    const int lane = tid & 31;
    const int warp = tid >> 5;
    const int warpM = warp & 1;
    const int warpN = warp >> 1;

    const int r0s = tid >> 2,         q0s = tid & 3;
    const int r1s = (tid + 256) >> 2;
    const uint32_t off0 = swz(r0s, q0s);
    const uint32_t off1 = swz(r1s, q0s);
    const __half* a0 = A  + (size_t)(rowBase + r0s) * K + q0s * 8;
    const __half* w0 = Wh + (size_t)(colBase + r0s) * K + q0s * 8;
    const __half* v0 = Wl + (size_t)(colBase + r0s) * K + q0s * 8;
    const __half* a1 = A  + (size_t)(rowBase + r1s) * K + q0s * 8;
    const __half* w1 = Wh + (size_t)(colBase + r1s) * K + q0s * 8;
    const __half* v1 = Wl + (size_t)(colBase + r1s) * K + q0s * 8;

    auto stage = [&](int s, int k0) {
        const uint32_t base = sb + s * F_STAGE;
        cp16(base + 0 * ARR_BYTES + off0, a0 + k0);
        cp16(base + 1 * ARR_BYTES + off0, w0 + k0);
        cp16(base + 2 * ARR_BYTES + off0, v0 + k0);
        cp16(base + 0 * ARR_BYTES + off1, a1 + k0);
        cp16(base + 1 * ARR_BYTES + off1, w1 + k0);
        cp16(base + 2 * ARR_BYTES + off1, v1 + k0);
        cp_commit();
    };

    const int ldrow = lane & 15;
    const int khalf = lane >> 4;
    uint32_t offA[2][4], offB[2][2];
#pragma unroll
    for (int kc = 0; kc < 2; kc++) {
        const int c = kc * 2 + khalf;
#pragma unroll
        for (int mi = 0; mi < 4; mi++)
            offA[kc][mi] = swz(warpM * 64 + mi * 16 + ldrow, c);
#pragma unroll
        for (int p = 0; p < 2; p++)
            offB[kc][p]  = swz(warpN * 32 + p * 16 + ldrow, c);
    }

    const int nt = K / 32;
    stage(0, 0);
    stage(1, 32);

    for (int it = 0; it < nt; it++) {
        if (it < nt - 1) cp_wait<1>(); else cp_wait<0>();
        __syncthreads();
        if (it + 2 < nt) stage((it + 2) % 3, (it + 2) * 32);

        const uint32_t base = sb + (it % 3) * F_STAGE;
#pragma unroll
        for (int kc = 0; kc < 2; kc++) {
            uint32_t bhi[4][2], blo[4][2];
#pragma unroll
            for (int p = 0; p < 2; p++) {
                uint32_t r0, r1, r2, r3;
                ldsm4(r0, r1, r2, r3, base + 1 * ARR_BYTES + offB[kc][p]);
                bhi[2 * p][0] = r0; bhi[2 * p + 1][0] = r1;
                bhi[2 * p][1] = r2; bhi[2 * p + 1][1] = r3;
                ldsm4(r0, r1, r2, r3, base + 2 * ARR_BYTES + offB[kc][p]);
                blo[2 * p][0] = r0; blo[2 * p + 1][0] = r1;
                blo[2 * p][1] = r2; blo[2 * p + 1][1] = r3;
            }
#pragma unroll
            for (int mi = 0; mi < 4; mi++) {
                uint32_t av[4];
                ldsm4(av[0], av[1], av[2], av[3], base + 0 * ARR_BYTES + offA[kc][mi]);
                // term-major: 4 independent MMAs between acc reuses
#pragma unroll
                for (int ni = 0; ni < 4; ni++) mma_fp16(acc[mi][ni], av, bhi[ni]);
#pragma unroll
                for (int ni = 0; ni < 4; ni++) mma_fp16(acc[mi][ni], av, blo[ni]);
            }
        }
    }
}

// ---------------------------------------------------------------------------
// FFN first GEMM (fp16): t = silu(h @ W1^T + b1), fp16 output
// ---------------------------------------------------------------------------
template<int K, int N>
__global__ __launch_bounds__(NTHREADS, 2) void gemm_ffn1(
    const __half* __restrict__ A,
    const __half* __restrict__ Wh, const __half* __restrict__ Wl,
    const float* __restrict__ bias, __half* __restrict__ C)
{
    extern __shared__ __align__(128) uint32_t smem[];
    const uint32_t sb = (uint32_t)__cvta_generic_to_shared(smem);
    const int rowBase = blockIdx.y * 128;
    const int colBase = blockIdx.x * 128;

    float acc[4][4][4];
#pragma unroll
    for (int mi = 0; mi < 4; mi++)
#pragma unroll
        for (int ni = 0; ni < 4; ni++)
#pragma unroll
            for (int r = 0; r < 4; r++) acc[mi][ni][r] = 0.0f;

    mainloop_fp16<K>(A, Wh, Wl, rowBase, colBase, sb, acc);

    const int lane = threadIdx.x & 31;
    const int warp = threadIdx.x >> 5;
    const int warpM = warp & 1, warpN = warp >> 1;
    const int g = lane >> 2, tg = lane & 3;
#pragma unroll
    for (int mi = 0; mi < 4; mi++) {
#pragma unroll
        for (int ni = 0; ni < 4; ni++) {
            int m0 = rowBase + warpM * 64 + mi * 16 + g;
            int n0 = colBase + warpN * 32 + ni * 8 + tg * 2;
            float bn0 = bias[n0], bn1 = bias[n0 + 1];
#pragma unroll
            for (int h = 0; h < 2; h++) {
                int m = m0 + h * 8;
                float u0 = silu_f(acc[mi][ni][2 * h + 0] + bn0);
                float u1 = silu_f(acc[mi][ni][2 * h + 1] + bn1);
                size_t idx = (size_t)m * N + n0;
                *(__half2*)(C + idx) =
                    __halves2half2(__float2half_rn(u0), __float2half_rn(u1));
            }
        }
    }
}

// ---------------------------------------------------------------------------
// FFN second GEMM (fp16): Q += t @ W2^T + b2  (residual, in place)
// ---------------------------------------------------------------------------
template<int K, int N>
__global__ __launch_bounds__(NTHREADS, 2) void gemm_ffn2(
    const __half* __restrict__ A,
    const __half* __restrict__ Wh, const __half* __restrict__ Wl,
    const float* __restrict__ bias, float* __restrict__ C)
{
    extern __shared__ __align__(128) uint32_t smem[];
    const uint32_t sb = (uint32_t)__cvta_generic_to_shared(smem);
    const int rowBase = blockIdx.y * 128;
    const int colBase = blockIdx.x * 128;

    float acc[4][4][4];
#pragma unroll
    for (int mi = 0; mi < 4; mi++)
#pragma unroll
        for (int ni = 0; ni < 4; ni++)
#pragma unroll
            for (int r = 0; r < 4; r++) acc[mi][ni][r] = 0.0f;

    mainloop_fp16<K>(A, Wh, Wl, rowBase, colBase, sb, acc);

    const int lane = threadIdx.x & 31;
    const int warp = threadIdx.x >> 5;
    const int warpM = warp & 1, warpN = warp >> 1;
    const int g = lane >> 2, tg = lane & 3;
#pragma unroll
    for (int mi = 0; mi < 4; mi++) {
#pragma unroll
        for (int ni = 0; ni < 4; ni++) {
            int m0 = rowBase + warpM * 64 + mi * 16 + g;
            int n0 = colBase + warpN * 32 + ni * 8 + tg * 2;
            float bn0 = bias[n0], bn1 = bias[n0 + 1];
#pragma unroll
            for (int h = 0; h < 2; h++) {
                int m = m0 + h * 8;
                size_t idx = (size_t)m * N + n0;
                C[idx]     = acc[mi][ni][2 * h + 0] + bn0 + C[idx];
                C[idx + 1] = acc[mi][ni][2 * h + 1] + bn1 + C[idx + 1];
            }
        }
    }
}

// ---------------------------------------------------------------------------
// Fused mu/sig GEMM (bf16x3) + attention gather (H precomputed in g_H).
// W is the packed interleaved [1024, 512] matrix (even rows mu, odd rows sig)
// so each epilogue pair (n0, n0+1) = (mu, sig) for token n = n0/2.
// ---------------------------------------------------------------------------
__global__ __launch_bounds__(NTHREADS, 2) void gemm_musig(
    const __nv_bfloat16* __restrict__ Ah, const __nv_bfloat16* __restrict__ Al,
    const __nv_bfloat16* __restrict__ Wh, const __nv_bfloat16* __restrict__ Wl,
    const float* __restrict__ mu_b, const float* __restrict__ sg_b,
    const float* __restrict__ G, float* __restrict__ Q)
{
    extern __shared__ __align__(128) uint32_t smem[];
    const uint32_t sb = (uint32_t)__cvta_generic_to_shared(smem);
    const int rowBase = blockIdx.y * 128;
    const int colBase = blockIdx.x * 128;

    float acc[4][4][4];
#pragma unroll
    for (int mi = 0; mi < 4; mi++)
#pragma unroll
        for (int ni = 0; ni < 4; ni++)
#pragma unroll
            for (int r = 0; r < 4; r++) acc[mi][ni][r] = 0.0f;

    mainloop_bf16<TDIM>(Ah, Al, Wh, Wl, rowBase, colBase, sb, acc);

    const int lane = threadIdx.x & 31;
    const int warp = threadIdx.x >> 5;
    const int warpM = warp & 1, warpN = warp >> 1;
    const int g = lane >> 2, tg = lane & 3;

#pragma unroll
    for (int ni = 0; ni < 4; ni++) {
        const int n0 = colBase + warpN * 32 + ni * 8 + tg * 2;   // even
        const int n  = n0 >> 1;
        const float bmu = mu_b[n], bsg = sg_b[n];
        const float4* G4 = (const float4*)(G + n * 8);
        const float4 gA = G4[0], gB = G4[1];
#pragma unroll
        for (int mi = 0; mi < 4; mi++) {
#pragma unroll
            for (int h = 0; h < 2; h++) {
                const int m = rowBase + warpM * 64 + mi * 16 + g + h * 8;
                const float muv = tanhf(acc[mi][ni][2 * h + 0] + bmu);
                const float sgv = acc[mi][ni][2 * h + 1] + bsg;
                const float rs  = 1.0f / fmaf(sgv, sgv, 1e-8f);
                const float4* H4 = (const float4*)(g_H + ((size_t)m * TDIM + n) * 8);
                const float4 hA = H4[0], hB = H4[1];
                float d, s = 0.0f;
                d = gA.x - muv; s += __expf(-0.5f * d * d * rs) * hA.x;
                d = gA.y - muv; s += __expf(-0.5f * d * d * rs) * hA.y;
                d = gA.z - muv; s += __expf(-0.5f * d * d * rs) * hA.z;
                d = gA.w - muv; s += __expf(-0.5f * d * d * rs) * hA.w;
                d = gB.x - muv; s += __expf(-0.5f * d * d * rs) * hB.x;
                d = gB.y - muv; s += __expf(-0.5f * d * d * rs) * hB.y;
                d = gB.z - muv; s += __expf(-0.5f * d * d * rs) * hB.z;
                d = gB.w - muv; s += __expf(-0.5f * d * d * rs) * hB.w;
                Q[(size_t)m * TDIM + n] += s;
            }
        }
    }
}

// ---------------------------------------------------------------------------
// One-shot weight split: musig -> bf16 hi/lo (interleave-packed),
// FFN weights -> fp16 hi/lo
// ---------------------------------------------------------------------------
__global__ __launch_bounds__(256) void wsplit_all(
    const float* __restrict__ mu_w, const float* __restrict__ sg_w,
    const float* __restrict__ a_w1, const float* __restrict__ a_w2,
    const float* __restrict__ m_w1, const float* __restrict__ m_w2)
{
    size_t i = (size_t)blockIdx.x * 256 + threadIdx.x;
    if (i < MS_TOTAL) {
        // packed musig: per attn block 1024x512 (2^19 elems)
        size_t a   = i >> 19;
        size_t rem = i & 524287;
        size_t r   = rem >> 9;          // interleaved row 0..1023
        size_t k   = rem & 511;
        size_t src = a * 262144 + (r >> 1) * 512 + k;
        float v = (r & 1) ? sg_w[src] : mu_w[src];
        __nv_bfloat16 h, l;
        split_bf16(v, h, l);
        g_wh[i] = h; g_wl[i] = l;
    }
    size_t j = i;   // same index space covers FW_TOTAL <= grid span
    if (j < FW_TOTAL) {
        float v;
        if (j < FAW2_OFF)      v = a_w1[j - FAW1_OFF];
        else if (j < FMW1_OFF) v = a_w2[j - FAW2_OFF];
        else if (j < FMW2_OFF) v = m_w1[j - FMW1_OFF];
        else                   v = m_w2[j - FMW2_OFF];
        __half h, l;
        split_fp16(v, h, l);
        g_fwh[j] = h; g_fwl[j] = l;
    }
}

// ---------------------------------------------------------------------------
// Prep: H[b,n,k] = cos(omega[n,k,:].x[b,:] + phase[n,k])  (once)
//       Q0[b,t]  = silu(x[b,:].l1_w[t,:] + l1_b[t])
// ---------------------------------------------------------------------------
__global__ __launch_bounds__(256) void prep_kernel(
    const float* __restrict__ x, const float* __restrict__ omega,
    const float* __restrict__ phase, const float* __restrict__ l1_w,
    const float* __restrict__ l1_b)
{
    int idx = blockIdx.x * 256 + threadIdx.x;     // b*T + n
    int b = idx >> 9, n = idx & 511;
    float x0 = x[b * 2 + 0], x1 = x[b * 2 + 1];
    float out[8];
#pragma unroll
    for (int k = 0; k < 8; k++) {
        int nk = n * 8 + k;
        float arg = fmaf(omega[nk * 2 + 0], x0,
                    fmaf(omega[nk * 2 + 1], x1, phase[nk]));
        out[k] = cosf(arg);
    }
    float4* H4 = (float4*)(g_H + (size_t)idx * 8);
    H4[0] = make_float4(out[0], out[1], out[2], out[3]);
    H4[1] = make_float4(out[4], out[5], out[6], out[7]);

    float p = fmaf(x0, l1_w[n * 2 + 0], fmaf(x1, l1_w[n * 2 + 1], l1_b[n]));
    g_Q[idx] = silu_f(p);
}

// ---------------------------------------------------------------------------
// LayerNorm over T=512, one warp per row.
// MODE 0: bf16 hi/lo split output (musig input)
// MODE 1: single fp16 output (FFN input)
// ---------------------------------------------------------------------------
template<int MODE>
__global__ __launch_bounds__(256) void ln_kernel(
    const float* __restrict__ X, const float* __restrict__ gam,
    const float* __restrict__ bet)
{
    int warp = threadIdx.x >> 5, lane = threadIdx.x & 31;
    int row = blockIdx.x * 8 + warp;
    const float4* xr = (const float4*)(X + (size_t)row * 512);
    float4 v[4];
    float s = 0.0f;
#pragma unroll
    for (int j = 0; j < 4; j++) {
        v[j] = xr[lane + j * 32];
        s += v[j].x + v[j].y + v[j].z + v[j].w;
    }
#pragma unroll
    for (int o = 16; o > 0; o >>= 1) s += __shfl_xor_sync(0xffffffffu, s, o);
    float m = s * (1.0f / 512.0f);
    float vs = 0.0f;
#pragma unroll
    for (int j = 0; j < 4; j++) {
        float dx = v[j].x - m, dy = v[j].y - m, dz = v[j].z - m, dw = v[j].w - m;
        vs += dx * dx + dy * dy + dz * dz + dw * dw;
    }
#pragma unroll
    for (int o = 16; o > 0; o >>= 1) vs += __shfl_xor_sync(0xffffffffu, vs, o);
    float inv = rsqrtf(vs * (1.0f / 512.0f) + 1e-5f);

    const float4* gr = (const float4*)gam;
    const float4* br = (const float4*)bet;
#pragma unroll
    for (int j = 0; j < 4; j++) {
        int c = lane + j * 32;
        float4 gg = gr[c], bb = br[c];
        float o0 = (v[j].x - m) * inv * gg.x + bb.x;
        float o1 = (v[j].y - m) * inv * gg.y + bb.y;
        float o2 = (v[j].z - m) * inv * gg.z + bb.z;
        float o3 = (v[j].w - m) * inv * gg.w + bb.w;
        if (MODE == 0) {
            __nv_bfloat162* yh = (__nv_bfloat162*)(g_hh + (size_t)row * 512);
            __nv_bfloat162* yl = (__nv_bfloat162*)(g_hl + (size_t)row * 512);
            __nv_bfloat16 h0, l0, h1, l1, h2, l2, h3, l3;
            split_bf16(o0, h0, l0); split_bf16(o1, h1, l1);
            split_bf16(o2, h2, l2); split_bf16(o3, h3, l3);
            yh[c * 2    ] = __halves2bfloat162(h0, h1);
            yh[c * 2 + 1] = __halves2bfloat162(h2, h3);
            yl[c * 2    ] = __halves2bfloat162(l0, l1);
            yl[c * 2 + 1] = __halves2bfloat162(l2, l3);
        } else {
            __half2* yf = (__half2*)(g_hf + (size_t)row * 512);
            yf[c * 2    ] = __halves2half2(__float2half_rn(o0), __float2half_rn(o1));
            yf[c * 2 + 1] = __halves2half2(__float2half_rn(o2), __float2half_rn(o3));
        }
    }
}

// ---------------------------------------------------------------------------
// Readout: out[b] = sum_t silu(Q[b,t]) * ro_w[t] + ro_b
// ---------------------------------------------------------------------------
__global__ __launch_bounds__(256) void final_kernel(
    const float* __restrict__ ro_w, const float* __restrict__ ro_b,
    float* __restrict__ out)
{
    int warp = threadIdx.x >> 5, lane = threadIdx.x & 31;
    int row = blockIdx.x * 8 + warp;
    const float4* q4 = (const float4*)(g_Q + (size_t)row * 512);
    const float4* w4 = (const float4*)ro_w;
    float s = 0.0f;
#pragma unroll
    for (int j = 0; j < 4; j++) {
        int c = lane + j * 32;
        float4 q = q4[c], w = w4[c];
        s += silu_f(q.x) * w.x + silu_f(q.y) * w.y
           + silu_f(q.z) * w.z + silu_f(q.w) * w.w;
    }
#pragma unroll
    for (int o = 16; o > 0; o >>= 1) s += __shfl_xor_sync(0xffffffffu, s, o);
    if (lane == 0) out[row] = s + ro_b[0];
}

// ---------------------------------------------------------------------------
// Host launcher
// ---------------------------------------------------------------------------
extern "C" void kernel_launch(void* const* d_in, const int* in_sizes, int n_in,
                              void* d_out, int out_size)
{
    const float* x      = (const float*)d_in[0];
    const float* omega  = (const float*)d_in[1];
    const float* G      = (const float*)d_in[2];
    const float* phase  = (const float*)d_in[3];
    const float* l1_w   = (const float*)d_in[4];
    const float* l1_b   = (const float*)d_in[5];
    const float* mu_w   = (const float*)d_in[6];
    const float* mu_b   = (const float*)d_in[7];
    const float* sg_w   = (const float*)d_in[8];
    const float* sg_b   = (const float*)d_in[9];
    const float* alnqg  = (const float*)d_in[10];
    const float* alnqb  = (const float*)d_in[11];
    const float* alnfg  = (const float*)d_in[12];
    const float* alnfb  = (const float*)d_in[13];
    const float* a_w1   = (const float*)d_in[14];
    const float* a_b1   = (const float*)d_in[15];
    const float* a_w2   = (const float*)d_in[16];
    const float* a_b2   = (const float*)d_in[17];
    const float* mln_g  = (const float*)d_in[18];
    const float* mln_b  = (const float*)d_in[19];
    const float* m_w1   = (const float*)d_in[20];
    const float* m_b1   = (const float*)d_in[21];
    const float* m_w2   = (const float*)d_in[22];
    const float* m_b2   = (const float*)d_in[23];
    const float* ro_w   = (const float*)d_in[24];
    const float* ro_b   = (const float*)d_in[25];
    float* out = (float*)d_out;

    __nv_bfloat16* wh; __nv_bfloat16* wl;
    __half* fwh; __half* fwl;
    float* Q;
    __nv_bfloat16* hh; __nv_bfloat16* hl;
    __half* hf; __half* tf;
    {
        void* p;
        cudaGetSymbolAddress(&p, g_wh);  wh  = (__nv_bfloat16*)p;
        cudaGetSymbolAddress(&p, g_wl);  wl  = (__nv_bfloat16*)p;
        cudaGetSymbolAddress(&p, g_fwh); fwh = (__half*)p;
        cudaGetSymbolAddress(&p, g_fwl); fwl = (__half*)p;
        cudaGetSymbolAddress(&p, g_Q);   Q   = (float*)p;
        cudaGetSymbolAddress(&p, g_hh);  hh  = (__nv_bfloat16*)p;
        cudaGetSymbolAddress(&p, g_hl);  hl  = (__nv_bfloat16*)p;
        cudaGetSymbolAddress(&p, g_hf);  hf  = (__half*)p;
        cudaGetSymbolAddress(&p, g_tf);  tf  = (__half*)p;
    }

    cudaFuncSetAttribute(gemm_musig,
                         cudaFuncAttributeMaxDynamicSharedMemorySize, B_SMEM);
    cudaFuncSetAttribute(gemm_ffn1<TDIM, FDIM>,
                         cudaFuncAttributeMaxDynamicSharedMemorySize, F_SMEM);
    cudaFuncSetAttribute(gemm_ffn2<FDIM, TDIM>,
                         cudaFuncAttributeMaxDynamicSharedMemorySize, F_SMEM);

    const int ew_blocks = (BATCH * TDIM) / 256;   // 16384
    const dim3 g_ms(1024 / 128, BATCH / 128);     // (8, 64)
    const dim3 g_f1(FDIM / 128, BATCH / 128);     // (16, 64)
    const dim3 g_f2(TDIM / 128, BATCH / 128);     // (4, 64)

    wsplit_all<<<FW_TOTAL / 256, 256>>>(mu_w, sg_w, a_w1, a_w2, m_w1, m_w2);
    prep_kernel<<<ew_blocks, 256>>>(x, omega, phase, l1_w, l1_b);

    for (int i = 0; i < NATTN; i++) {
        const size_t wms = (size_t)i * 1024 * 512;
        const size_t wft = (size_t)i * FDIM * TDIM;
        ln_kernel<0><<<BATCH / 8, 256>>>(Q, alnqg + i * TDIM, alnqb + i * TDIM);
        gemm_musig<<<g_ms, NTHREADS, B_SMEM>>>(
            hh, hl, wh + wms, wl + wms,
            mu_b + i * TDIM, sg_b + i * TDIM, G, Q);
        ln_kernel<1><<<BATCH / 8, 256>>>(Q, alnfg + i * TDIM, alnfb + i * TDIM);
        gemm_ffn1<TDIM, FDIM><<<g_f1, NTHREADS, F_SMEM>>>(
            hf, fwh + FAW1_OFF + wft, fwl + FAW1_OFF + wft,
            a_b1 + i * FDIM, tf);
        gemm_ffn2<FDIM, TDIM><<<g_f2, NTHREADS, F_SMEM>>>(
            tf, fwh + FAW2_OFF + wft, fwl + FAW2_OFF + wft,
            a_b2 + i * TDIM, Q);
    }
    for (int i = 0; i < NMLP; i++) {
        const size_t wft = (size_t)i * FDIM * TDIM;
        ln_kernel<1><<<BATCH / 8, 256>>>(Q, mln_g + i * TDIM, mln_b + i * TDIM);
        gemm_ffn1<TDIM, FDIM><<<g_f1, NTHREADS, F_SMEM>>>(
            hf, fwh + FMW1_OFF + wft, fwl + FMW1_OFF + wft,
            m_b1 + i * FDIM, tf);
        gemm_ffn2<FDIM, TDIM><<<g_f2, NTHREADS, F_SMEM>>>(
            tf, fwh + FMW2_OFF + wft, fwl + FMW2_OFF + wft,
            m_b2 + i * TDIM, Q);
    }
    final_kernel<<<BATCH / 8, 256>>>(ro_w, ro_b, out);
}

// round 17
// speedup vs baseline: 2.3085x; 1.4605x over previous
#include <cuda_runtime.h>
#include <cuda_bf16.h>
#include <cuda_fp16.h>
#include <cstdint>
#include <math.h>

// ---------------------------------------------------------------------------
// Problem constants
// ---------------------------------------------------------------------------
#define BATCH 8192
#define TDIM  512
#define FDIM  2048
#define NATTN 4
#define NMLP  2

// musig weight scratch (fp16 hi/lo): packed mu/sig, per attn block 1024x512,
// rows interleaved (even row r -> mu_w[r/2], odd row r -> sg_w[r/2])
#define MS_TOTAL 2097152
// FFN weight scratch (single fp16) offsets
#define FAW1_OFF 0
#define FAW2_OFF 4194304
#define FMW1_OFF 8388608
#define FMW2_OFF 10485760
#define FW_TOTAL 12582912

// ---------------------------------------------------------------------------
// Device scratch (static — no allocation at launch time)
// ---------------------------------------------------------------------------
__device__ __half g_wh[MS_TOTAL];        // musig weight hi (fp16)
__device__ __half g_wl[MS_TOTAL];        // musig weight lo (fp16, subnormal ok)
__device__ __half g_fw[FW_TOTAL];        // FFN weights (single fp16)
__device__ float  g_Q [BATCH * TDIM];    // residual stream
__device__ float  g_H [BATCH * TDIM * 8];// RFF tokens (precomputed, fp32)
__device__ __half g_hf[BATCH * TDIM];    // LN output (fp16 activations)
__device__ __half g_tf[BATCH * FDIM];    // FFN mid (fp16)

// ---------------------------------------------------------------------------
// Helpers
// ---------------------------------------------------------------------------
__device__ __forceinline__ float silu_f(float x) {
    return x / (1.0f + __expf(-x));
}

__device__ __forceinline__ void split_fp16(float x, __half& hi, __half& lo) {
    hi = __float2half_rn(x);
    lo = __float2half_rn(x - __half2float(hi));
}

__device__ __forceinline__ void mma_fp16(float* d, const uint32_t* a, const uint32_t* b) {
    asm volatile(
        "mma.sync.aligned.m16n8k16.row.col.f32.f16.f16.f32 "
        "{%0,%1,%2,%3}, {%4,%5,%6,%7}, {%8,%9}, {%0,%1,%2,%3};\n"
        : "+f"(d[0]), "+f"(d[1]), "+f"(d[2]), "+f"(d[3])
        : "r"(a[0]), "r"(a[1]), "r"(a[2]), "r"(a[3]), "r"(b[0]), "r"(b[1]));
}

__device__ __forceinline__ void cp16(uint32_t dst, const void* src) {
    asm volatile("cp.async.cg.shared.global [%0], [%1], 16;\n" :: "r"(dst), "l"(src));
}
__device__ __forceinline__ void cp_commit() {
    asm volatile("cp.async.commit_group;\n");
}
template<int N> __device__ __forceinline__ void cp_wait() {
    asm volatile("cp.async.wait_group %0;\n" :: "n"(N));
}

__device__ __forceinline__ void ldsm4(uint32_t& r0, uint32_t& r1, uint32_t& r2,
                                      uint32_t& r3, uint32_t addr) {
    asm volatile("ldmatrix.sync.aligned.m8n8.x4.shared.b16 {%0,%1,%2,%3}, [%4];\n"
                 : "=r"(r0), "=r"(r1), "=r"(r2), "=r"(r3) : "r"(addr));
}

// XOR-swizzled smem layout: per array, row r holds 32 elems(16b) = 64B =
// 4 chunks of 16B; logical chunk c lives at physical chunk c ^ ((r>>1)&3).
// Both the 8-row ldmatrix phases and the staging writes cover all 32 banks
// exactly: conflict-free.
__device__ __forceinline__ uint32_t swz(int r, int c) {
    return (uint32_t)(r * 64 + ((c ^ ((r >> 1) & 3)) * 16));
}

#define ARR_BYTES 8192                 // 128 rows x 64 B
#define NTHREADS 256

// ---------------------------------------------------------------------------
// fp16 one-side-split mainloop (musig): A single fp16, W = Wh + Wl fp16.
//   acc += A*Wh + A*Wl (2 MMAs). R10 scheme: 256 thr, 2 CTA/SM, warp grid
//   2m x 4n, warp tile 64x32, 3-stage cp.async ring, one __syncthreads per
//   K-tile, prefetch distance 2. 88KB smem traffic / tile.
// ---------------------------------------------------------------------------
#define MS_STAGE (3 * ARR_BYTES)       // 24576: A, Wh, Wl
#define MS_SMEM  (3 * MS_STAGE)        // 73728

template<int K>
__device__ __forceinline__ void mainloop_w2(
    const __half* __restrict__ A,
    const __half* __restrict__ Wh, const __half* __restrict__ Wl,
    int rowBase, int colBase, uint32_t sb, float acc[4][4][4])
{
    const int tid  = threadIdx.x;
    const int lane = tid & 31;
    const int warp = tid >> 5;
    const int warpM = warp & 1;
    const int warpN = warp >> 1;

    const int r0s = tid >> 2,         q0s = tid & 3;
    const int r1s = (tid + 256) >> 2;
    const uint32_t off0 = swz(r0s, q0s);
    const uint32_t off1 = swz(r1s, q0s);
    const __half* a0 = A  + (size_t)(rowBase + r0s) * K + q0s * 8;
    const __half* w0 = Wh + (size_t)(colBase + r0s) * K + q0s * 8;
    const __half* v0 = Wl + (size_t)(colBase + r0s) * K + q0s * 8;
    const __half* a1 = A  + (size_t)(rowBase + r1s) * K + q0s * 8;
    const __half* w1 = Wh + (size_t)(colBase + r1s) * K + q0s * 8;
    const __half* v1 = Wl + (size_t)(colBase + r1s) * K + q0s * 8;

    auto stage = [&](int s, int k0) {
        const uint32_t base = sb + s * MS_STAGE;
        cp16(base + 0 * ARR_BYTES + off0, a0 + k0);
        cp16(base + 1 * ARR_BYTES + off0, w0 + k0);
        cp16(base + 2 * ARR_BYTES + off0, v0 + k0);
        cp16(base + 0 * ARR_BYTES + off1, a1 + k0);
        cp16(base + 1 * ARR_BYTES + off1, w1 + k0);
        cp16(base + 2 * ARR_BYTES + off1, v1 + k0);
        cp_commit();
    };

    const int ldrow = lane & 15;
    const int khalf = lane >> 4;
    uint32_t offA[2][4], offB[2][2];
#pragma unroll
    for (int kc = 0; kc < 2; kc++) {
        const int c = kc * 2 + khalf;
#pragma unroll
        for (int mi = 0; mi < 4; mi++)
            offA[kc][mi] = swz(warpM * 64 + mi * 16 + ldrow, c);
#pragma unroll
        for (int p = 0; p < 2; p++)
            offB[kc][p]  = swz(warpN * 32 + p * 16 + ldrow, c);
    }

    const int nt = K / 32;
    stage(0, 0);
    stage(1, 32);

    for (int it = 0; it < nt; it++) {
        if (it < nt - 1) cp_wait<1>(); else cp_wait<0>();
        __syncthreads();
        if (it + 2 < nt) stage((it + 2) % 3, (it + 2) * 32);

        const uint32_t base = sb + (it % 3) * MS_STAGE;
#pragma unroll
        for (int kc = 0; kc < 2; kc++) {
            uint32_t bhi[4][2], blo[4][2];
#pragma unroll
            for (int p = 0; p < 2; p++) {
                uint32_t r0, r1, r2, r3;
                ldsm4(r0, r1, r2, r3, base + 1 * ARR_BYTES + offB[kc][p]);
                bhi[2 * p][0] = r0; bhi[2 * p + 1][0] = r1;
                bhi[2 * p][1] = r2; bhi[2 * p + 1][1] = r3;
                ldsm4(r0, r1, r2, r3, base + 2 * ARR_BYTES + offB[kc][p]);
                blo[2 * p][0] = r0; blo[2 * p + 1][0] = r1;
                blo[2 * p][1] = r2; blo[2 * p + 1][1] = r3;
            }
#pragma unroll
            for (int mi = 0; mi < 4; mi++) {
                uint32_t av[4];
                ldsm4(av[0], av[1], av[2], av[3], base + 0 * ARR_BYTES + offA[kc][mi]);
                // term-major: 4 independent MMAs between acc reuses
#pragma unroll
                for (int ni = 0; ni < 4; ni++) mma_fp16(acc[mi][ni], av, bhi[ni]);
#pragma unroll
                for (int ni = 0; ni < 4; ni++) mma_fp16(acc[mi][ni], av, blo[ni]);
            }
        }
    }
}

// ---------------------------------------------------------------------------
// fp16 single-weight mainloop (FFN): A and W single fp16, 1 MMA per pair.
//   64KB smem traffic / tile. Same ring/barrier scheme.
// ---------------------------------------------------------------------------
#define F_STAGE (2 * ARR_BYTES)        // 16384: A, W
#define F_SMEM  (3 * F_STAGE)          // 49152

template<int K>
__device__ __forceinline__ void mainloop_w1(
    const __half* __restrict__ A, const __half* __restrict__ W,
    int rowBase, int colBase, uint32_t sb, float acc[4][4][4])
{
    const int tid  = threadIdx.x;
    const int lane = tid & 31;
    const int warp = tid >> 5;
    const int warpM = warp & 1;
    const int warpN = warp >> 1;

    const int r0s = tid >> 2,         q0s = tid & 3;
    const int r1s = (tid + 256) >> 2;
    const uint32_t off0 = swz(r0s, q0s);
    const uint32_t off1 = swz(r1s, q0s);
    const __half* a0 = A + (size_t)(rowBase + r0s) * K + q0s * 8;
    const __half* w0 = W + (size_t)(colBase + r0s) * K + q0s * 8;
    const __half* a1 = A + (size_t)(rowBase + r1s) * K + q0s * 8;
    const __half* w1 = W + (size_t)(colBase + r1s) * K + q0s * 8;

    auto stage = [&](int s, int k0) {
        const uint32_t base = sb + s * F_STAGE;
        cp16(base + 0 * ARR_BYTES + off0, a0 + k0);
        cp16(base + 1 * ARR_BYTES + off0, w0 + k0);
        cp16(base + 0 * ARR_BYTES + off1, a1 + k0);
        cp16(base + 1 * ARR_BYTES + off1, w1 + k0);
        cp_commit();
    };

    const int ldrow = lane & 15;
    const int khalf = lane >> 4;
    uint32_t offA[2][4], offB[2][2];
#pragma unroll
    for (int kc = 0; kc < 2; kc++) {
        const int c = kc * 2 + khalf;
#pragma unroll
        for (int mi = 0; mi < 4; mi++)
            offA[kc][mi] = swz(warpM * 64 + mi * 16 + ldrow, c);
#pragma unroll
        for (int p = 0; p < 2; p++)
            offB[kc][p]  = swz(warpN * 32 + p * 16 + ldrow, c);
    }

    const int nt = K / 32;
    stage(0, 0);
    stage(1, 32);

    for (int it = 0; it < nt; it++) {
        if (it < nt - 1) cp_wait<1>(); else cp_wait<0>();
        __syncthreads();
        if (it + 2 < nt) stage((it + 2) % 3, (it + 2) * 32);

        const uint32_t base = sb + (it % 3) * F_STAGE;
#pragma unroll
        for (int kc = 0; kc < 2; kc++) {
            uint32_t bv[4][2];
#pragma unroll
            for (int p = 0; p < 2; p++) {
                uint32_t r0, r1, r2, r3;
                ldsm4(r0, r1, r2, r3, base + 1 * ARR_BYTES + offB[kc][p]);
                bv[2 * p][0] = r0; bv[2 * p + 1][0] = r1;
                bv[2 * p][1] = r2; bv[2 * p + 1][1] = r3;
            }
#pragma unroll
            for (int mi = 0; mi < 4; mi++) {
                uint32_t av[4];
                ldsm4(av[0], av[1], av[2], av[3], base + 0 * ARR_BYTES + offA[kc][mi]);
#pragma unroll
                for (int ni = 0; ni < 4; ni++) mma_fp16(acc[mi][ni], av, bv[ni]);
            }
        }
    }
}

// ---------------------------------------------------------------------------
// FFN first GEMM: t = silu(h @ W1^T + b1), fp16 output
// ---------------------------------------------------------------------------
template<int K, int N>
__global__ __launch_bounds__(NTHREADS, 2) void gemm_ffn1(
    const __half* __restrict__ A, const __half* __restrict__ W,
    const float* __restrict__ bias, __half* __restrict__ C)
{
    extern __shared__ __align__(128) uint32_t smem[];
    const uint32_t sb = (uint32_t)__cvta_generic_to_shared(smem);
    const int rowBase = blockIdx.y * 128;
    const int colBase = blockIdx.x * 128;

    float acc[4][4][4];
#pragma unroll
    for (int mi = 0; mi < 4; mi++)
#pragma unroll
        for (int ni = 0; ni < 4; ni++)
#pragma unroll
            for (int r = 0; r < 4; r++) acc[mi][ni][r] = 0.0f;

    mainloop_w1<K>(A, W, rowBase, colBase, sb, acc);

    const int lane = threadIdx.x & 31;
    const int warp = threadIdx.x >> 5;
    const int warpM = warp & 1, warpN = warp >> 1;
    const int g = lane >> 2, tg = lane & 3;
#pragma unroll
    for (int mi = 0; mi < 4; mi++) {
#pragma unroll
        for (int ni = 0; ni < 4; ni++) {
            int m0 = rowBase + warpM * 64 + mi * 16 + g;
            int n0 = colBase + warpN * 32 + ni * 8 + tg * 2;
            float bn0 = bias[n0], bn1 = bias[n0 + 1];
#pragma unroll
            for (int h = 0; h < 2; h++) {
                int m = m0 + h * 8;
                float u0 = silu_f(acc[mi][ni][2 * h + 0] + bn0);
                float u1 = silu_f(acc[mi][ni][2 * h + 1] + bn1);
                size_t idx = (size_t)m * N + n0;
                *(__half2*)(C + idx) =
                    __halves2half2(__float2half_rn(u0), __float2half_rn(u1));
            }
        }
    }
}

// ---------------------------------------------------------------------------
// FFN second GEMM: Q += t @ W2^T + b2  (residual, in place)
// ---------------------------------------------------------------------------
template<int K, int N>
__global__ __launch_bounds__(NTHREADS, 2) void gemm_ffn2(
    const __half* __restrict__ A, const __half* __restrict__ W,
    const float* __restrict__ bias, float* __restrict__ C)
{
    extern __shared__ __align__(128) uint32_t smem[];
    const uint32_t sb = (uint32_t)__cvta_generic_to_shared(smem);
    const int rowBase = blockIdx.y * 128;
    const int colBase = blockIdx.x * 128;

    float acc[4][4][4];
#pragma unroll
    for (int mi = 0; mi < 4; mi++)
#pragma unroll
        for (int ni = 0; ni < 4; ni++)
#pragma unroll
            for (int r = 0; r < 4; r++) acc[mi][ni][r] = 0.0f;

    mainloop_w1<K>(A, W, rowBase, colBase, sb, acc);

    const int lane = threadIdx.x & 31;
    const int warp = threadIdx.x >> 5;
    const int warpM = warp & 1, warpN = warp >> 1;
    const int g = lane >> 2, tg = lane & 3;
#pragma unroll
    for (int mi = 0; mi < 4; mi++) {
#pragma unroll
        for (int ni = 0; ni < 4; ni++) {
            int m0 = rowBase + warpM * 64 + mi * 16 + g;
            int n0 = colBase + warpN * 32 + ni * 8 + tg * 2;
            float bn0 = bias[n0], bn1 = bias[n0 + 1];
#pragma unroll
            for (int h = 0; h < 2; h++) {
                int m = m0 + h * 8;
                size_t idx = (size_t)m * N + n0;
                C[idx]     = acc[mi][ni][2 * h + 0] + bn0 + C[idx];
                C[idx + 1] = acc[mi][ni][2 * h + 1] + bn1 + C[idx + 1];
            }
        }
    }
}

// ---------------------------------------------------------------------------
// Fused mu/sig GEMM (fp16 one-side split) + attention gather (H in g_H).
// W is the packed interleaved [1024, 512] matrix (even rows mu, odd rows sig)
// so each epilogue pair (n0, n0+1) = (mu, sig) for token n = n0/2.
// ---------------------------------------------------------------------------
__global__ __launch_bounds__(NTHREADS, 2) void gemm_musig(
    const __half* __restrict__ A,
    const __half* __restrict__ Wh, const __half* __restrict__ Wl,
    const float* __restrict__ mu_b, const float* __restrict__ sg_b,
    const float* __restrict__ G, float* __restrict__ Q)
{
    extern __shared__ __align__(128) uint32_t smem[];
    const uint32_t sb = (uint32_t)__cvta_generic_to_shared(smem);
    const int rowBase = blockIdx.y * 128;
    const int colBase = blockIdx.x * 128;

    float acc[4][4][4];
#pragma unroll
    for (int mi = 0; mi < 4; mi++)
#pragma unroll
        for (int ni = 0; ni < 4; ni++)
#pragma unroll
            for (int r = 0; r < 4; r++) acc[mi][ni][r] = 0.0f;

    mainloop_w2<TDIM>(A, Wh, Wl, rowBase, colBase, sb, acc);

    const int lane = threadIdx.x & 31;
    const int warp = threadIdx.x >> 5;
    const int warpM = warp & 1, warpN = warp >> 1;
    const int g = lane >> 2, tg = lane & 3;

#pragma unroll
    for (int ni = 0; ni < 4; ni++) {
        const int n0 = colBase + warpN * 32 + ni * 8 + tg * 2;   // even
        const int n  = n0 >> 1;
        const float bmu = mu_b[n], bsg = sg_b[n];
        const float4* G4 = (const float4*)(G + n * 8);
        const float4 gA = G4[0], gB = G4[1];
#pragma unroll
        for (int mi = 0; mi < 4; mi++) {
#pragma unroll
            for (int h = 0; h < 2; h++) {
                const int m = rowBase + warpM * 64 + mi * 16 + g + h * 8;
                const float muv = tanhf(acc[mi][ni][2 * h + 0] + bmu);
                const float sgv = acc[mi][ni][2 * h + 1] + bsg;
                const float rs  = 1.0f / fmaf(sgv, sgv, 1e-8f);
                const float4* H4 = (const float4*)(g_H + ((size_t)m * TDIM + n) * 8);
                const float4 hA = H4[0], hB = H4[1];
                float d, s = 0.0f;
                d = gA.x - muv; s += __expf(-0.5f * d * d * rs) * hA.x;
                d = gA.y - muv; s += __expf(-0.5f * d * d * rs) * hA.y;
                d = gA.z - muv; s += __expf(-0.5f * d * d * rs) * hA.z;
                d = gA.w - muv; s += __expf(-0.5f * d * d * rs) * hA.w;
                d = gB.x - muv; s += __expf(-0.5f * d * d * rs) * hB.x;
                d = gB.y - muv; s += __expf(-0.5f * d * d * rs) * hB.y;
                d = gB.z - muv; s += __expf(-0.5f * d * d * rs) * hB.z;
                d = gB.w - muv; s += __expf(-0.5f * d * d * rs) * hB.w;
                Q[(size_t)m * TDIM + n] += s;
            }
        }
    }
}

// ---------------------------------------------------------------------------
// One-shot weight prep: musig -> fp16 hi/lo (interleave-packed),
// FFN weights -> single fp16
// ---------------------------------------------------------------------------
__global__ __launch_bounds__(256) void wsplit_all(
    const float* __restrict__ mu_w, const float* __restrict__ sg_w,
    const float* __restrict__ a_w1, const float* __restrict__ a_w2,
    const float* __restrict__ m_w1, const float* __restrict__ m_w2)
{
    size_t i = (size_t)blockIdx.x * 256 + threadIdx.x;
    if (i < MS_TOTAL) {
        // packed musig: per attn block 1024x512 (2^19 elems)
        size_t a   = i >> 19;
        size_t rem = i & 524287;
        size_t r   = rem >> 9;          // interleaved row 0..1023
        size_t k   = rem & 511;
        size_t src = a * 262144 + (r >> 1) * 512 + k;
        float v = (r & 1) ? sg_w[src] : mu_w[src];
        __half h, l;
        split_fp16(v, h, l);
        g_wh[i] = h; g_wl[i] = l;
    }
    if (i < FW_TOTAL) {
        float v;
        if (i < FAW2_OFF)      v = a_w1[i - FAW1_OFF];
        else if (i < FMW1_OFF) v = a_w2[i - FAW2_OFF];
        else if (i < FMW2_OFF) v = m_w1[i - FMW1_OFF];
        else                   v = m_w2[i - FMW2_OFF];
        g_fw[i] = __float2half_rn(v);
    }
}

// ---------------------------------------------------------------------------
// Prep: H[b,n,k] = cos(omega[n,k,:].x[b,:] + phase[n,k])  (once)
//       Q0[b,t]  = silu(x[b,:].l1_w[t,:] + l1_b[t])
// ---------------------------------------------------------------------------
__global__ __launch_bounds__(256) void prep_kernel(
    const float* __restrict__ x, const float* __restrict__ omega,
    const float* __restrict__ phase, const float* __restrict__ l1_w,
    const float* __restrict__ l1_b)
{
    int idx = blockIdx.x * 256 + threadIdx.x;     // b*T + n
    int b = idx >> 9, n = idx & 511;
    float x0 = x[b * 2 + 0], x1 = x[b * 2 + 1];
    float out[8];
#pragma unroll
    for (int k = 0; k < 8; k++) {
        int nk = n * 8 + k;
        float arg = fmaf(omega[nk * 2 + 0], x0,
                    fmaf(omega[nk * 2 + 1], x1, phase[nk]));
        out[k] = cosf(arg);
    }
    float4* H4 = (float4*)(g_H + (size_t)idx * 8);
    H4[0] = make_float4(out[0], out[1], out[2], out[3]);
    H4[1] = make_float4(out[4], out[5], out[6], out[7]);

    float p = fmaf(x0, l1_w[n * 2 + 0], fmaf(x1, l1_w[n * 2 + 1], l1_b[n]));
    g_Q[idx] = silu_f(p);
}

// ---------------------------------------------------------------------------
// LayerNorm over T=512, one warp per row; single fp16 output (g_hf)
// ---------------------------------------------------------------------------
__global__ __launch_bounds__(256) void ln_kernel(
    const float* __restrict__ X, const float* __restrict__ gam,
    const float* __restrict__ bet)
{
    int warp = threadIdx.x >> 5, lane = threadIdx.x & 31;
    int row = blockIdx.x * 8 + warp;
    const float4* xr = (const float4*)(X + (size_t)row * 512);
    float4 v[4];
    float s = 0.0f;
#pragma unroll
    for (int j = 0; j < 4; j++) {
        v[j] = xr[lane + j * 32];
        s += v[j].x + v[j].y + v[j].z + v[j].w;
    }
#pragma unroll
    for (int o = 16; o > 0; o >>= 1) s += __shfl_xor_sync(0xffffffffu, s, o);
    float m = s * (1.0f / 512.0f);
    float vs = 0.0f;
#pragma unroll
    for (int j = 0; j < 4; j++) {
        float dx = v[j].x - m, dy = v[j].y - m, dz = v[j].z - m, dw = v[j].w - m;
        vs += dx * dx + dy * dy + dz * dz + dw * dw;
    }
#pragma unroll
    for (int o = 16; o > 0; o >>= 1) vs += __shfl_xor_sync(0xffffffffu, vs, o);
    float inv = rsqrtf(vs * (1.0f / 512.0f) + 1e-5f);

    const float4* gr = (const float4*)gam;
    const float4* br = (const float4*)bet;
    __half2* yf = (__half2*)(g_hf + (size_t)row * 512);
#pragma unroll
    for (int j = 0; j < 4; j++) {
        int c = lane + j * 32;
        float4 gg = gr[c], bb = br[c];
        float o0 = (v[j].x - m) * inv * gg.x + bb.x;
        float o1 = (v[j].y - m) * inv * gg.y + bb.y;
        float o2 = (v[j].z - m) * inv * gg.z + bb.z;
        float o3 = (v[j].w - m) * inv * gg.w + bb.w;
        yf[c * 2    ] = __halves2half2(__float2half_rn(o0), __float2half_rn(o1));
        yf[c * 2 + 1] = __halves2half2(__float2half_rn(o2), __float2half_rn(o3));
    }
}

// ---------------------------------------------------------------------------
// Readout: out[b] = sum_t silu(Q[b,t]) * ro_w[t] + ro_b
// ---------------------------------------------------------------------------
__global__ __launch_bounds__(256) void final_kernel(
    const float* __restrict__ ro_w, const float* __restrict__ ro_b,
    float* __restrict__ out)
{
    int warp = threadIdx.x >> 5, lane = threadIdx.x & 31;
    int row = blockIdx.x * 8 + warp;
    const float4* q4 = (const float4*)(g_Q + (size_t)row * 512);
    const float4* w4 = (const float4*)ro_w;
    float s = 0.0f;
#pragma unroll
    for (int j = 0; j < 4; j++) {
        int c = lane + j * 32;
        float4 q = q4[c], w = w4[c];
        s += silu_f(q.x) * w.x + silu_f(q.y) * w.y
           + silu_f(q.z) * w.z + silu_f(q.w) * w.w;
    }
#pragma unroll
    for (int o = 16; o > 0; o >>= 1) s += __shfl_xor_sync(0xffffffffu, s, o);
    if (lane == 0) out[row] = s + ro_b[0];
}

// ---------------------------------------------------------------------------
// Host launcher
// ---------------------------------------------------------------------------
extern "C" void kernel_launch(void* const* d_in, const int* in_sizes, int n_in,
                              void* d_out, int out_size)
{
    const float* x      = (const float*)d_in[0];
    const float* omega  = (const float*)d_in[1];
    const float* G      = (const float*)d_in[2];
    const float* phase  = (const float*)d_in[3];
    const float* l1_w   = (const float*)d_in[4];
    const float* l1_b   = (const float*)d_in[5];
    const float* mu_w   = (const float*)d_in[6];
    const float* mu_b   = (const float*)d_in[7];
    const float* sg_w   = (const float*)d_in[8];
    const float* sg_b   = (const float*)d_in[9];
    const float* alnqg  = (const float*)d_in[10];
    const float* alnqb  = (const float*)d_in[11];
    const float* alnfg  = (const float*)d_in[12];
    const float* alnfb  = (const float*)d_in[13];
    const float* a_w1   = (const float*)d_in[14];
    const float* a_b1   = (const float*)d_in[15];
    const float* a_w2   = (const float*)d_in[16];
    const float* a_b2   = (const float*)d_in[17];
    const float* mln_g  = (const float*)d_in[18];
    const float* mln_b  = (const float*)d_in[19];
    const float* m_w1   = (const float*)d_in[20];
    const float* m_b1   = (const float*)d_in[21];
    const float* m_w2   = (const float*)d_in[22];
    const float* m_b2   = (const float*)d_in[23];
    const float* ro_w   = (const float*)d_in[24];
    const float* ro_b   = (const float*)d_in[25];
    float* out = (float*)d_out;

    __half* wh; __half* wl; __half* fw;
    float* Q;
    __half* hf; __half* tf;
    {
        void* p;
        cudaGetSymbolAddress(&p, g_wh); wh = (__half*)p;
        cudaGetSymbolAddress(&p, g_wl); wl = (__half*)p;
        cudaGetSymbolAddress(&p, g_fw); fw = (__half*)p;
        cudaGetSymbolAddress(&p, g_Q);  Q  = (float*)p;
        cudaGetSymbolAddress(&p, g_hf); hf = (__half*)p;
        cudaGetSymbolAddress(&p, g_tf); tf = (__half*)p;
    }

    cudaFuncSetAttribute(gemm_musig,
                         cudaFuncAttributeMaxDynamicSharedMemorySize, MS_SMEM);
    cudaFuncSetAttribute(gemm_ffn1<TDIM, FDIM>,
                         cudaFuncAttributeMaxDynamicSharedMemorySize, F_SMEM);
    cudaFuncSetAttribute(gemm_ffn2<FDIM, TDIM>,
                         cudaFuncAttributeMaxDynamicSharedMemorySize, F_SMEM);

    const int ew_blocks = (BATCH * TDIM) / 256;   // 16384
    const dim3 g_ms(1024 / 128, BATCH / 128);     // (8, 64)
    const dim3 g_f1(FDIM / 128, BATCH / 128);     // (16, 64)
    const dim3 g_f2(TDIM / 128, BATCH / 128);     // (4, 64)

    wsplit_all<<<FW_TOTAL / 256, 256>>>(mu_w, sg_w, a_w1, a_w2, m_w1, m_w2);
    prep_kernel<<<ew_blocks, 256>>>(x, omega, phase, l1_w, l1_b);

    for (int i = 0; i < NATTN; i++) {
        const size_t wms = (size_t)i * 1024 * 512;
        const size_t wft = (size_t)i * FDIM * TDIM;
        ln_kernel<<<BATCH / 8, 256>>>(Q, alnqg + i * TDIM, alnqb + i * TDIM);
        gemm_musig<<<g_ms, NTHREADS, MS_SMEM>>>(
            hf, wh + wms, wl + wms,
            mu_b + i * TDIM, sg_b + i * TDIM, G, Q);
        ln_kernel<<<BATCH / 8, 256>>>(Q, alnfg + i * TDIM, alnfb + i * TDIM);
        gemm_ffn1<TDIM, FDIM><<<g_f1, NTHREADS, F_SMEM>>>(
            hf, fw + FAW1_OFF + wft, a_b1 + i * FDIM, tf);
        gemm_ffn2<FDIM, TDIM><<<g_f2, NTHREADS, F_SMEM>>>(
            tf, fw + FAW2_OFF + wft, a_b2 + i * TDIM, Q);
    }
    for (int i = 0; i < NMLP; i++) {
        const size_t wft = (size_t)i * FDIM * TDIM;
        ln_kernel<<<BATCH / 8, 256>>>(Q, mln_g + i * TDIM, mln_b + i * TDIM);
        gemm_ffn1<TDIM, FDIM><<<g_f1, NTHREADS, F_SMEM>>>(
            hf, fw + FMW1_OFF + wft, m_b1 + i * FDIM, tf);
        gemm_ffn2<FDIM, TDIM><<<g_f2, NTHREADS, F_SMEM>>>(
            tf, fw + FMW2_OFF + wft, m_b2 + i * TDIM, Q);
    }
    final_kernel<<<BATCH / 8, 256>>>(ro_w, ro_b, out);
}